// round 1
// baseline (speedup 1.0000x reference)
#include <cuda_runtime.h>
#include <cuda_bf16.h>
#include <cstdint>

// ---------------------------------------------------------------------------
// Problem constants: B=1, S=2048, D=1024, H=16, hd=64, DFF=4096
// ---------------------------------------------------------------------------
#define S_  2048
#define D_  1024
#define H_  16
#define HD_ 64
#define DFF_ 4096

// ---------------------------------------------------------------------------
// Device scratch (static globals; no allocations allowed)
// ---------------------------------------------------------------------------
__device__ float g_x  [S_ * D_];          // LN output (reused for ln1 and ln2)
__device__ float g_q  [S_ * D_];
__device__ float g_k  [S_ * D_];
__device__ float g_v  [S_ * D_];
__device__ float g_att[S_ * D_];
__device__ float g_y  [S_ * D_];          // residual-1 output
__device__ float g_h1 [S_ * DFF_];        // FFN hidden
__device__ float g_p  [(long)H_ * S_ * S_]; // scores / entmax probs (256 MB)

// ---------------------------------------------------------------------------
// LayerNorm: sigma = unbiased std (ddof=1) + 1e-6 ; out = (x-mu)/sigma * a + b
// one block per row, 256 threads, 4 elems/thread (D=1024)
// ---------------------------------------------------------------------------
__global__ __launch_bounds__(256)
void ln_kernel(const float* __restrict__ X, const float* __restrict__ ga,
               const float* __restrict__ gb, float* __restrict__ O)
{
    __shared__ float sm_s[8], sm_q[8];
    const long row = blockIdx.x;
    const int tid = threadIdx.x;
    const float4 v = ((const float4*)(X + row * D_))[tid];

    float s  = v.x + v.y + v.z + v.w;
    float sq = v.x*v.x + v.y*v.y + v.z*v.z + v.w*v.w;
    #pragma unroll
    for (int o = 16; o > 0; o >>= 1) {
        s  += __shfl_xor_sync(0xffffffffu, s,  o);
        sq += __shfl_xor_sync(0xffffffffu, sq, o);
    }
    if ((tid & 31) == 0) { sm_s[tid >> 5] = s; sm_q[tid >> 5] = sq; }
    __syncthreads();
    if (tid == 0) {
        float rs = 0.f, rq = 0.f;
        #pragma unroll
        for (int w = 0; w < 8; w++) { rs += sm_s[w]; rq += sm_q[w]; }
        sm_s[0] = rs; sm_q[0] = rq;
    }
    __syncthreads();
    const float sum = sm_s[0], sumsq = sm_q[0];
    const float mu  = sum * (1.0f / D_);
    const float var = fmaxf((sumsq - mu * mu * (float)D_) * (1.0f / (D_ - 1)), 0.0f);
    const float inv = 1.0f / (sqrtf(var) + 1e-6f);

    const float4 a4 = ((const float4*)ga)[tid];
    const float4 b4 = ((const float4*)gb)[tid];
    float4 o;
    o.x = (v.x - mu) * inv * a4.x + b4.x;
    o.y = (v.y - mu) * inv * a4.y + b4.y;
    o.z = (v.z - mu) * inv * a4.z + b4.z;
    o.w = (v.w - mu) * inv * a4.w + b4.w;
    ((float4*)(O + row * D_))[tid] = o;
}

// ---------------------------------------------------------------------------
// Generic tiled SGEMM.
//   BT=true : C[m,n] = sum_k A[m,k] * B[n,k]   (B is [N,K] row-major, e.g. weights)
//   BT=false: C[m,n] = sum_k A[m,k] * B[k,n]   (B is [K,N] row-major, e.g. PV)
// Batched via blockIdx.z with element strides sA/sB/sC.
// Epilogue modes:
//   0: plain    1: +bias[n]    2: relu(+bias[n])
//   3: +bias[n] + resid[m,n]   4: mask[n] ? v*alpha : -1e9
// All dims assumed divisible by tile sizes (true for this problem).
// ---------------------------------------------------------------------------
template<int BM, int BN, int BK, int TM, int TN, bool BT>
__global__ __launch_bounds__(256)
void gemm_kernel(const float* __restrict__ A, const float* __restrict__ B,
                 float* __restrict__ C,
                 int K, int lda, int ldb, int ldc,
                 long sA, long sB, long sC,
                 float alpha,
                 const float* __restrict__ bias,
                 const float* __restrict__ resid,
                 const int* __restrict__ mask,
                 int mode)
{
    __shared__ float As[BK][BM];
    __shared__ float Bs[BK][BN];

    const int z = blockIdx.z;
    A += (long)z * sA;
    B += (long)z * sB;
    C += (long)z * sC;

    const int m0 = blockIdx.y * BM;
    const int n0 = blockIdx.x * BN;
    const int tid = threadIdx.x;
    const int NT = BN / TN;          // threads along n
    const int tx = tid % NT;
    const int ty = tid / NT;

    float acc[TM][TN];
    #pragma unroll
    for (int i = 0; i < TM; i++)
        #pragma unroll
        for (int j = 0; j < TN; j++) acc[i][j] = 0.f;

    for (int k0 = 0; k0 < K; k0 += BK) {
        // ---- load A tile (BM x BK), float4 along k, store transposed ----
        #pragma unroll
        for (int l = 0; l < (BM * BK) / (256 * 4); l++) {
            const int idx = (tid + l * 256) * 4;
            const int m = idx / BK, k = idx % BK;
            const float4 v = *(const float4*)(A + (long)(m0 + m) * lda + k0 + k);
            As[k + 0][m] = v.x; As[k + 1][m] = v.y;
            As[k + 2][m] = v.z; As[k + 3][m] = v.w;
        }
        // ---- load B tile ----
        if (BT) {
            #pragma unroll
            for (int l = 0; l < (BN * BK) / (256 * 4); l++) {
                const int idx = (tid + l * 256) * 4;
                const int n = idx / BK, k = idx % BK;
                const float4 v = *(const float4*)(B + (long)(n0 + n) * ldb + k0 + k);
                Bs[k + 0][n] = v.x; Bs[k + 1][n] = v.y;
                Bs[k + 2][n] = v.z; Bs[k + 3][n] = v.w;
            }
        } else {
            #pragma unroll
            for (int l = 0; l < (BN * BK) / (256 * 4); l++) {
                const int idx = (tid + l * 256) * 4;
                const int k = idx / BN, n = idx % BN;
                *(float4*)&Bs[k][n] =
                    *(const float4*)(B + (long)(k0 + k) * ldb + n0 + n);
            }
        }
        __syncthreads();

        #pragma unroll
        for (int kk = 0; kk < BK; kk++) {
            float a[TM], b[TN];
            #pragma unroll
            for (int i = 0; i < TM; i += 4)
                *(float4*)&a[i] = *(const float4*)&As[kk][ty * TM + i];
            #pragma unroll
            for (int j = 0; j < TN; j += 4)
                *(float4*)&b[j] = *(const float4*)&Bs[kk][tx * TN + j];
            #pragma unroll
            for (int i = 0; i < TM; i++)
                #pragma unroll
                for (int j = 0; j < TN; j++)
                    acc[i][j] = fmaf(a[i], b[j], acc[i][j]);
        }
        __syncthreads();
    }

    // ---- epilogue ----
    #pragma unroll
    for (int i = 0; i < TM; i++) {
        const long row = m0 + ty * TM + i;
        #pragma unroll
        for (int j = 0; j < TN; j++) {
            const int col = n0 + tx * TN + j;
            float v = acc[i][j];
            if (mode == 1)      v += bias[col];
            else if (mode == 2) { v += bias[col]; v = fmaxf(v, 0.f); }
            else if (mode == 3) v += bias[col] + resid[row * ldc + col];
            else if (mode == 4) v = mask[col] ? v * alpha : -1e9f;
            C[row * ldc + col] = v;
        }
    }
}

// ---------------------------------------------------------------------------
// entmax-1.5 over one row of 2048 scores (in place).
// x = s/2 - max ; solve f(tau)=sum relu(x-tau)^2 = 1 by 32-step bisection
// (f strictly decreasing; exact root == sort-based tau_star of the reference).
// ---------------------------------------------------------------------------
__global__ __launch_bounds__(256)
void entmax_kernel(float* __restrict__ P)
{
    __shared__ float sm[8];
    const long row = blockIdx.x;
    float* p = P + row * (long)S_;
    const int tid = threadIdx.x;

    float x[8];
    {
        const float4 v0 = ((const float4*)p)[tid * 2 + 0];
        const float4 v1 = ((const float4*)p)[tid * 2 + 1];
        x[0] = v0.x; x[1] = v0.y; x[2] = v0.z; x[3] = v0.w;
        x[4] = v1.x; x[5] = v1.y; x[6] = v1.z; x[7] = v1.w;
    }
    float mx = -3.4e38f;
    #pragma unroll
    for (int i = 0; i < 8; i++) { x[i] *= 0.5f; mx = fmaxf(mx, x[i]); }

    // ---- block max ----
    #pragma unroll
    for (int o = 16; o > 0; o >>= 1) mx = fmaxf(mx, __shfl_xor_sync(0xffffffffu, mx, o));
    if ((tid & 31) == 0) sm[tid >> 5] = mx;
    __syncthreads();
    if (tid == 0) {
        float r = sm[0];
        #pragma unroll
        for (int w = 1; w < 8; w++) r = fmaxf(r, sm[w]);
        sm[0] = r;
    }
    __syncthreads();
    mx = sm[0];
    __syncthreads();
    #pragma unroll
    for (int i = 0; i < 8; i++) x[i] -= mx;

    // ---- bisection: tau in [-1, 0]; f(-1) >= 1 (element at max contributes 1) ----
    float lo = -1.0f, hi = 0.0f;
    for (int it = 0; it < 32; it++) {
        const float mid = 0.5f * (lo + hi);
        float s = 0.f;
        #pragma unroll
        for (int i = 0; i < 8; i++) {
            const float t = fmaxf(x[i] - mid, 0.f);
            s = fmaf(t, t, s);
        }
        #pragma unroll
        for (int o = 16; o > 0; o >>= 1) s += __shfl_xor_sync(0xffffffffu, s, o);
        if ((tid & 31) == 0) sm[tid >> 5] = s;
        __syncthreads();
        if (tid == 0) {
            float r = 0.f;
            #pragma unroll
            for (int w = 0; w < 8; w++) r += sm[w];
            sm[0] = r;
        }
        __syncthreads();
        s = sm[0];
        __syncthreads();
        if (s >= 1.0f) lo = mid; else hi = mid;
    }
    const float tau = 0.5f * (lo + hi);

    float o[8];
    #pragma unroll
    for (int i = 0; i < 8; i++) {
        const float t = fmaxf(x[i] - tau, 0.f);
        o[i] = t * t;
    }
    float4 w0, w1;
    w0.x = o[0]; w0.y = o[1]; w0.z = o[2]; w0.w = o[3];
    w1.x = o[4]; w1.y = o[5]; w1.z = o[6]; w1.w = o[7];
    ((float4*)p)[tid * 2 + 0] = w0;
    ((float4*)p)[tid * 2 + 1] = w1;
}

// ---------------------------------------------------------------------------
// Launch
// ---------------------------------------------------------------------------
static float* sym_addr(const void* sym)
{
    void* p = nullptr;
    cudaGetSymbolAddress(&p, sym);
    return (float*)p;
}

extern "C" void kernel_launch(void* const* d_in, const int* in_sizes, int n_in,
                              void* d_out, int out_size)
{
    const float* inputs = (const float*)d_in[0];
    const int*   mask   = (const int*)  d_in[1];
    const float* wq = (const float*)d_in[2];  const float* bq = (const float*)d_in[3];
    const float* wk = (const float*)d_in[4];  const float* bk = (const float*)d_in[5];
    const float* wv = (const float*)d_in[6];  const float* bv = (const float*)d_in[7];
    const float* wo = (const float*)d_in[8];  const float* bo = (const float*)d_in[9];
    const float* ln1_a = (const float*)d_in[10]; const float* ln1_b = (const float*)d_in[11];
    const float* w1 = (const float*)d_in[12]; const float* b1 = (const float*)d_in[13];
    const float* w2 = (const float*)d_in[14]; const float* b2 = (const float*)d_in[15];
    const float* ln2_a = (const float*)d_in[16]; const float* ln2_b = (const float*)d_in[17];
    float* out = (float*)d_out;

    float* x   = sym_addr(g_x);
    float* q   = sym_addr(g_q);
    float* k   = sym_addr(g_k);
    float* v   = sym_addr(g_v);
    float* att = sym_addr(g_att);
    float* y   = sym_addr(g_y);
    float* h1  = sym_addr(g_h1);
    float* p   = sym_addr(g_p);

    const dim3 blk(256);

    // --- sublayer 1: pre-norm ---
    ln_kernel<<<S_, blk>>>(inputs, ln1_a, ln1_b, x);

    // --- Q/K/V projections: [2048,1024] = x @ W^T + b ---
    gemm_kernel<128,128,8,8,8,true><<<dim3(D_/128, S_/128, 1), blk>>>(
        x, wq, q, D_, D_, D_, D_, 0, 0, 0, 1.f, bq, nullptr, nullptr, 1);
    gemm_kernel<128,128,8,8,8,true><<<dim3(D_/128, S_/128, 1), blk>>>(
        x, wk, k, D_, D_, D_, D_, 0, 0, 0, 1.f, bk, nullptr, nullptr, 1);
    gemm_kernel<128,128,8,8,8,true><<<dim3(D_/128, S_/128, 1), blk>>>(
        x, wv, v, D_, D_, D_, D_, 0, 0, 0, 1.f, bv, nullptr, nullptr, 1);

    // --- scores: per head, [2048,2048] = Q_h K_h^T / 8, key-masked ---
    gemm_kernel<128,128,8,8,8,true><<<dim3(S_/128, S_/128, H_), blk>>>(
        q, k, p, HD_, D_, D_, S_,
        (long)HD_, (long)HD_, (long)S_ * S_,
        0.125f, nullptr, nullptr, mask, 4);

    // --- entmax-1.5, in place ---
    entmax_kernel<<<H_ * S_, blk>>>(p);

    // --- attended: per head, [2048,64] = P_h @ V_h ---
    gemm_kernel<128,64,16,8,4,false><<<dim3(1, S_/128, H_), blk>>>(
        p, v, att, S_, S_, D_, D_,
        (long)S_ * S_, (long)HD_, (long)HD_,
        1.f, nullptr, nullptr, nullptr, 0);

    // --- output projection + residual: y = inputs + att @ wo^T + bo ---
    gemm_kernel<128,128,8,8,8,true><<<dim3(D_/128, S_/128, 1), blk>>>(
        att, wo, y, D_, D_, D_, D_, 0, 0, 0, 1.f, bo, inputs, nullptr, 3);

    // --- sublayer 2: pre-norm ---
    ln_kernel<<<S_, blk>>>(y, ln2_a, ln2_b, x);

    // --- FFN1: [2048,4096] = relu(x @ w1^T + b1) ---
    gemm_kernel<128,128,8,8,8,true><<<dim3(DFF_/128, S_/128, 1), blk>>>(
        x, w1, h1, D_, D_, D_, DFF_, 0, 0, 0, 1.f, b1, nullptr, nullptr, 2);

    // --- FFN2 + residual -> out: [2048,1024] = y + h1 @ w2^T + b2 ---
    gemm_kernel<128,128,8,8,8,true><<<dim3(D_/128, S_/128, 1), blk>>>(
        h1, w2, out, DFF_, DFF_, DFF_, D_, 0, 0, 0, 1.f, b2, y, nullptr, 3);
}

// round 3
// speedup vs baseline: 2.1892x; 2.1892x over previous
#include <cuda_runtime.h>
#include <cuda_bf16.h>
#include <cstdint>

#define S_   2048
#define D_   1024
#define H_   16
#define HD_  64
#define DFF_ 4096

// ---------------------------------------------------------------------------
// Device scratch (no runtime allocation allowed)
// ---------------------------------------------------------------------------
__device__ float         g_s  [(long)H_ * S_ * S_];     // fp32 scores (256MB)
__device__ __nv_bfloat16 g_phi[(long)H_ * S_ * S_];     // entmax probs hi
__device__ __nv_bfloat16 g_plo[(long)H_ * S_ * S_];     // entmax probs lo
__device__ __nv_bfloat16 g_xhi[S_ * D_],  g_xlo[S_ * D_];
__device__ __nv_bfloat16 g_qhi[S_ * D_],  g_qlo[S_ * D_];
__device__ __nv_bfloat16 g_khi[S_ * D_],  g_klo[S_ * D_];
__device__ __nv_bfloat16 g_vthi[S_ * D_], g_vtlo[S_ * D_];   // [h][64][S]
__device__ __nv_bfloat16 g_ahi[S_ * D_],  g_alo[S_ * D_];    // attended
__device__ float         g_y  [S_ * D_];
__device__ __nv_bfloat16 g_h1hi[S_ * DFF_], g_h1lo[S_ * DFF_];
__device__ __nv_bfloat16 g_wqhi[D_ * D_],  g_wqlo[D_ * D_];
__device__ __nv_bfloat16 g_wkhi[D_ * D_],  g_wklo[D_ * D_];
__device__ __nv_bfloat16 g_wvhi[D_ * D_],  g_wvlo[D_ * D_];
__device__ __nv_bfloat16 g_wohi[D_ * D_],  g_wolo[D_ * D_];
__device__ __nv_bfloat16 g_w1hi[DFF_ * D_], g_w1lo[DFF_ * D_];
__device__ __nv_bfloat16 g_w2hi[D_ * DFF_], g_w2lo[D_ * DFF_];

// ---------------------------------------------------------------------------
// PTX helpers (baseline PTX only — sm_80-class instructions)
// ---------------------------------------------------------------------------
__device__ __forceinline__ uint32_t smem_u32(const void* p) {
    uint32_t a;
    asm("{ .reg .u64 t; cvta.to.shared.u64 t, %1; cvt.u32.u64 %0, t; }"
        : "=r"(a) : "l"(p));
    return a;
}

#define CP16(dst, src) \
    asm volatile("cp.async.cg.shared.global [%0], [%1], 16;" \
                 :: "r"(dst), "l"(src))

#define LDSM4(r, addr) \
    asm volatile("ldmatrix.sync.aligned.m8n8.x4.shared.b16 {%0,%1,%2,%3}, [%4];" \
                 : "=r"((r)[0]), "=r"((r)[1]), "=r"((r)[2]), "=r"((r)[3]) \
                 : "r"(addr))

#define MMA16816(d, a, b) \
    asm volatile("mma.sync.aligned.m16n8k16.row.col.f32.bf16.bf16.f32 " \
                 "{%0,%1,%2,%3}, {%4,%5,%6,%7}, {%8,%9}, {%0,%1,%2,%3};" \
                 : "+f"((d)[0]), "+f"((d)[1]), "+f"((d)[2]), "+f"((d)[3]) \
                 : "r"((a)[0]), "r"((a)[1]), "r"((a)[2]), "r"((a)[3]), \
                   "r"((b)[0]), "r"((b)[1]))

__device__ __forceinline__ void split_store(float v, __nv_bfloat16* hi,
                                            __nv_bfloat16* lo, long idx) {
    __nv_bfloat16 h = __float2bfloat16(v);
    hi[idx] = h;
    lo[idx] = __float2bfloat16(v - __bfloat162float(h));
}

// ---------------------------------------------------------------------------
// fp32 -> (bf16 hi, bf16 lo) conversion (weights)
// ---------------------------------------------------------------------------
__global__ __launch_bounds__(256)
void split_f32(const float* __restrict__ x, __nv_bfloat16* __restrict__ hi,
               __nv_bfloat16* __restrict__ lo, int n)
{
    int i = blockIdx.x * 256 + threadIdx.x;
    if (i < n) {
        float v = x[i];
        __nv_bfloat16 h = __float2bfloat16(v);
        hi[i] = h;
        lo[i] = __float2bfloat16(v - __bfloat162float(h));
    }
}

// ---------------------------------------------------------------------------
// LayerNorm (ddof=1 std + 1e-6) -> split-bf16 output
// ---------------------------------------------------------------------------
__global__ __launch_bounds__(256)
void ln_kernel(const float* __restrict__ X, const float* __restrict__ ga,
               const float* __restrict__ gb,
               __nv_bfloat16* __restrict__ OH, __nv_bfloat16* __restrict__ OL)
{
    __shared__ float sm_s[8], sm_q[8];
    const long row = blockIdx.x;
    const int tid = threadIdx.x;
    const float4 v = ((const float4*)(X + row * D_))[tid];

    float s  = v.x + v.y + v.z + v.w;
    float sq = v.x*v.x + v.y*v.y + v.z*v.z + v.w*v.w;
    #pragma unroll
    for (int o = 16; o > 0; o >>= 1) {
        s  += __shfl_xor_sync(0xffffffffu, s,  o);
        sq += __shfl_xor_sync(0xffffffffu, sq, o);
    }
    if ((tid & 31) == 0) { sm_s[tid >> 5] = s; sm_q[tid >> 5] = sq; }
    __syncthreads();
    if (tid == 0) {
        float rs = 0.f, rq = 0.f;
        #pragma unroll
        for (int w = 0; w < 8; w++) { rs += sm_s[w]; rq += sm_q[w]; }
        sm_s[0] = rs; sm_q[0] = rq;
    }
    __syncthreads();
    const float mu  = sm_s[0] * (1.0f / D_);
    const float var = fmaxf((sm_q[0] - mu * mu * (float)D_) * (1.0f / (D_ - 1)), 0.0f);
    const float inv = 1.0f / (sqrtf(var) + 1e-6f);

    const float4 a4 = ((const float4*)ga)[tid];
    const float4 b4 = ((const float4*)gb)[tid];
    float o[4];
    o[0] = (v.x - mu) * inv * a4.x + b4.x;
    o[1] = (v.y - mu) * inv * a4.y + b4.y;
    o[2] = (v.z - mu) * inv * a4.z + b4.z;
    o[3] = (v.w - mu) * inv * a4.w + b4.w;
    const long base = row * D_ + (long)tid * 4;
    #pragma unroll
    for (int i = 0; i < 4; i++) split_store(o[i], OH, OL, base + i);
}

// ---------------------------------------------------------------------------
// entmax-1.5 over one row of 2048 fp32 scores -> split-bf16 probs
// ---------------------------------------------------------------------------
__global__ __launch_bounds__(256)
void entmax_kernel(const float* __restrict__ SC,
                   __nv_bfloat16* __restrict__ PH, __nv_bfloat16* __restrict__ PL)
{
    __shared__ float sm[8];
    const long row = blockIdx.x;
    const float* p = SC + row * (long)S_;
    const int tid = threadIdx.x;

    float x[8];
    {
        const float4 v0 = ((const float4*)p)[tid * 2 + 0];
        const float4 v1 = ((const float4*)p)[tid * 2 + 1];
        x[0] = v0.x; x[1] = v0.y; x[2] = v0.z; x[3] = v0.w;
        x[4] = v1.x; x[5] = v1.y; x[6] = v1.z; x[7] = v1.w;
    }
    float mx = -3.4e38f;
    #pragma unroll
    for (int i = 0; i < 8; i++) { x[i] *= 0.5f; mx = fmaxf(mx, x[i]); }

    #pragma unroll
    for (int o = 16; o > 0; o >>= 1) mx = fmaxf(mx, __shfl_xor_sync(0xffffffffu, mx, o));
    if ((tid & 31) == 0) sm[tid >> 5] = mx;
    __syncthreads();
    if (tid == 0) {
        float r = sm[0];
        #pragma unroll
        for (int w = 1; w < 8; w++) r = fmaxf(r, sm[w]);
        sm[0] = r;
    }
    __syncthreads();
    mx = sm[0];
    __syncthreads();
    #pragma unroll
    for (int i = 0; i < 8; i++) x[i] -= mx;

    float lo = -1.0f, hi = 0.0f;
    for (int it = 0; it < 30; it++) {
        const float mid = 0.5f * (lo + hi);
        float s = 0.f;
        #pragma unroll
        for (int i = 0; i < 8; i++) {
            const float t = fmaxf(x[i] - mid, 0.f);
            s = fmaf(t, t, s);
        }
        #pragma unroll
        for (int o = 16; o > 0; o >>= 1) s += __shfl_xor_sync(0xffffffffu, s, o);
        if ((tid & 31) == 0) sm[tid >> 5] = s;
        __syncthreads();
        if (tid == 0) {
            float r = 0.f;
            #pragma unroll
            for (int w = 0; w < 8; w++) r += sm[w];
            sm[0] = r;
        }
        __syncthreads();
        s = sm[0];
        __syncthreads();
        if (s >= 1.0f) lo = mid; else hi = mid;
    }
    const float tau = 0.5f * (lo + hi);

    __nv_bfloat16 hb[8], lb[8];
    #pragma unroll
    for (int i = 0; i < 8; i++) {
        const float t = fmaxf(x[i] - tau, 0.f);
        const float o = t * t;
        hb[i] = __float2bfloat16(o);
        lb[i] = __float2bfloat16(o - __bfloat162float(hb[i]));
    }
    const long base = row * (long)S_ + (long)tid * 8;
    *(uint4*)(PH + base) = *(const uint4*)hb;
    *(uint4*)(PL + base) = *(const uint4*)lb;
}

// ---------------------------------------------------------------------------
// Warp-MMA split-bf16 GEMM.  C[m,n] = sum_k A[m,k]*B[n,k]  (K-major both)
// bf16x3: acc += Ah*Bh + Al*Bh + Ah*Bl  (single fp32 accumulator)
// CTA tile: 128 x BN x 32, 8 warps, double-buffered cp.async.
// MODE: 0 scores (mask+scale -> fp32), 1 bias -> split, 2 bias -> split V^T,
//       3 plain -> split att (col += z*64), 4 bias+resid -> fp32,
//       5 bias+relu -> split
// ---------------------------------------------------------------------------
template<int BN, int MODE>
__global__ __launch_bounds__(256)
void gemm_mma(const __nv_bfloat16* __restrict__ Ahi, const __nv_bfloat16* __restrict__ Alo,
              int lda, long zsA,
              const __nv_bfloat16* __restrict__ Bhi, const __nv_bfloat16* __restrict__ Blo,
              int ldb, long zsB,
              int K,
              float* __restrict__ Cf, long zsC, int ldc,
              __nv_bfloat16* __restrict__ Chi, __nv_bfloat16* __restrict__ Clo,
              const float* __restrict__ bias, const float* __restrict__ resid,
              const int* __restrict__ mask, float alpha)
{
    constexpr int BM = 128, BK = 32;
    constexpr int WARPS_N = (BN == 128) ? 4 : 2;
    constexpr int WARPS_M = 8 / WARPS_N;
    constexpr int WM = BM / WARPS_M;        // 64 or 32
    constexpr int WN = BN / WARPS_N;        // 32
    constexpr int MI = WM / 16;             // 4 or 2
    constexpr int NJ = WN / 8;              // 4
    constexpr int LDSB   = 80;              // smem row stride bytes (40 bf16)
    constexpr int ABYTES = BM * LDSB;       // one A array (hi or lo)
    constexpr int BBYTES = BN * LDSB;
    constexpr int STAGE  = 2 * ABYTES + 2 * BBYTES;

    extern __shared__ char smem[];
    const uint32_t sb = smem_u32(smem);

    const int tid  = threadIdx.x;
    const int wid  = tid >> 5;
    const int lane = tid & 31;
    const int z    = blockIdx.z;
    const int m0   = blockIdx.y * BM;
    const int n0   = blockIdx.x * BN;
    const int wtm  = (wid / WARPS_N) * WM;
    const int wtn  = (wid % WARPS_N) * WN;

    const __nv_bfloat16* ah = Ahi + (long)z * zsA + (long)m0 * lda;
    const __nv_bfloat16* al = Alo + (long)z * zsA + (long)m0 * lda;
    const __nv_bfloat16* bh = Bhi + (long)z * zsB + (long)n0 * ldb;
    const __nv_bfloat16* bl = Blo + (long)z * zsB + (long)n0 * ldb;

    float acc[MI][NJ][4];
    #pragma unroll
    for (int i = 0; i < MI; i++)
        #pragma unroll
        for (int j = 0; j < NJ; j++)
            #pragma unroll
            for (int r = 0; r < 4; r++) acc[i][j][r] = 0.f;

    const int nc = K / BK;

    auto load_stage = [&](int st, int c) {
        const uint32_t base = sb + st * STAGE;
        const int k0 = c * BK;
        #pragma unroll
        for (int it = 0; it < (BM * 4) / 256; it++) {
            const int ci = tid + it * 256;
            const int r = ci >> 2, q = ci & 3;
            const uint32_t d = base + r * LDSB + q * 16;
            CP16(d,          ah + (long)r * lda + k0 + q * 8);
            CP16(d + ABYTES, al + (long)r * lda + k0 + q * 8);
        }
        #pragma unroll
        for (int it = 0; it < (BN * 4) / 256; it++) {
            const int ci = tid + it * 256;
            const int r = ci >> 2, q = ci & 3;
            const uint32_t d = base + 2 * ABYTES + r * LDSB + q * 16;
            CP16(d,          bh + (long)r * ldb + k0 + q * 8);
            CP16(d + BBYTES, bl + (long)r * ldb + k0 + q * 8);
        }
        asm volatile("cp.async.commit_group;");
    };

    load_stage(0, 0);

    for (int c = 0; c < nc; c++) {
        if (c + 1 < nc) {
            load_stage((c + 1) & 1, c + 1);
            asm volatile("cp.async.wait_group 1;");
        } else {
            asm volatile("cp.async.wait_group 0;");
        }
        __syncthreads();

        const uint32_t base = sb + (c & 1) * STAGE;
        #pragma unroll
        for (int ks = 0; ks < 2; ks++) {
            uint32_t afh[MI][4], afl[MI][4];
            #pragma unroll
            for (int i = 0; i < MI; i++) {
                const int row = wtm + i * 16 + (lane & 15);
                const int kc  = ks * 16 + ((lane >> 4) << 3);
                const uint32_t ad = base + row * LDSB + kc * 2;
                LDSM4(afh[i], ad);
                LDSM4(afl[i], ad + ABYTES);
            }
            uint32_t bfh[NJ][2], bfl[NJ][2];
            #pragma unroll
            for (int jp = 0; jp < NJ / 2; jp++) {
                const int nrow = wtn + jp * 16 + (lane & 7) + ((lane & 16) ? 8 : 0);
                const int kc   = ks * 16 + ((lane & 8) ? 8 : 0);
                const uint32_t bd = base + 2 * ABYTES + nrow * LDSB + kc * 2;
                uint32_t t[4];
                LDSM4(t, bd);
                bfh[2*jp][0] = t[0]; bfh[2*jp][1] = t[1];
                bfh[2*jp+1][0] = t[2]; bfh[2*jp+1][1] = t[3];
                LDSM4(t, bd + BBYTES);
                bfl[2*jp][0] = t[0]; bfl[2*jp][1] = t[1];
                bfl[2*jp+1][0] = t[2]; bfl[2*jp+1][1] = t[3];
            }
            #pragma unroll
            for (int i = 0; i < MI; i++)
                #pragma unroll
                for (int j = 0; j < NJ; j++) {
                    MMA16816(acc[i][j], afh[i], bfh[j]);
                    MMA16816(acc[i][j], afl[i], bfh[j]);
                    MMA16816(acc[i][j], afh[i], bfl[j]);
                }
        }
        __syncthreads();
    }

    // ---- epilogue ----
    #pragma unroll
    for (int i = 0; i < MI; i++)
        #pragma unroll
        for (int j = 0; j < NJ; j++)
            #pragma unroll
            for (int r = 0; r < 4; r++) {
                const int row = m0 + wtm + i * 16 + (lane >> 2) + (r >> 1) * 8;
                const int col = n0 + wtn + j * 8 + (lane & 3) * 2 + (r & 1);
                float v = acc[i][j][r];
                if (MODE == 0) {
                    v = mask[col] ? v * alpha : -1e9f;
                    (Cf + (long)z * zsC)[(long)row * ldc + col] = v;
                } else if (MODE == 1) {
                    v += bias[col];
                    split_store(v, Chi, Clo, (long)row * ldc + col);
                } else if (MODE == 2) {
                    v += bias[col];
                    split_store(v, Chi, Clo, (long)col * S_ + row);
                } else if (MODE == 3) {
                    split_store(v, Chi, Clo, (long)row * ldc + z * 64 + col);
                } else if (MODE == 4) {
                    const long idx = (long)row * ldc + col;
                    v += bias[col] + resid[idx];
                    Cf[idx] = v;
                } else {  // MODE 5
                    v = fmaxf(v + bias[col], 0.f);
                    split_store(v, Chi, Clo, (long)row * ldc + col);
                }
            }
}

// ---------------------------------------------------------------------------
// Launch
// ---------------------------------------------------------------------------
template<typename T>
static T* sym(const void* s) {
    void* p = nullptr;
    cudaGetSymbolAddress(&p, s);
    return (T*)p;
}

extern "C" void kernel_launch(void* const* d_in, const int* in_sizes, int n_in,
                              void* d_out, int out_size)
{
    const float* inputs = (const float*)d_in[0];
    const int*   mask   = (const int*)  d_in[1];
    const float* wq = (const float*)d_in[2];  const float* bq = (const float*)d_in[3];
    const float* wk = (const float*)d_in[4];  const float* bk = (const float*)d_in[5];
    const float* wv = (const float*)d_in[6];  const float* bv = (const float*)d_in[7];
    const float* wo = (const float*)d_in[8];  const float* bo = (const float*)d_in[9];
    const float* ln1_a = (const float*)d_in[10]; const float* ln1_b = (const float*)d_in[11];
    const float* w1 = (const float*)d_in[12]; const float* b1 = (const float*)d_in[13];
    const float* w2 = (const float*)d_in[14]; const float* b2 = (const float*)d_in[15];
    const float* ln2_a = (const float*)d_in[16]; const float* ln2_b = (const float*)d_in[17];
    float* out = (float*)d_out;

    float* s = sym<float>(g_s);
    __nv_bfloat16 *phi = sym<__nv_bfloat16>(g_phi), *plo = sym<__nv_bfloat16>(g_plo);
    __nv_bfloat16 *xhi = sym<__nv_bfloat16>(g_xhi), *xlo = sym<__nv_bfloat16>(g_xlo);
    __nv_bfloat16 *qhi = sym<__nv_bfloat16>(g_qhi), *qlo = sym<__nv_bfloat16>(g_qlo);
    __nv_bfloat16 *khi = sym<__nv_bfloat16>(g_khi), *klo = sym<__nv_bfloat16>(g_klo);
    __nv_bfloat16 *vthi = sym<__nv_bfloat16>(g_vthi), *vtlo = sym<__nv_bfloat16>(g_vtlo);
    __nv_bfloat16 *athi = sym<__nv_bfloat16>(g_ahi), *atlo = sym<__nv_bfloat16>(g_alo);
    float* y = sym<float>(g_y);
    __nv_bfloat16 *h1hi = sym<__nv_bfloat16>(g_h1hi), *h1lo = sym<__nv_bfloat16>(g_h1lo);
    __nv_bfloat16 *wqhi = sym<__nv_bfloat16>(g_wqhi), *wqlo = sym<__nv_bfloat16>(g_wqlo);
    __nv_bfloat16 *wkhi = sym<__nv_bfloat16>(g_wkhi), *wklo = sym<__nv_bfloat16>(g_wklo);
    __nv_bfloat16 *wvhi = sym<__nv_bfloat16>(g_wvhi), *wvlo = sym<__nv_bfloat16>(g_wvlo);
    __nv_bfloat16 *wohi = sym<__nv_bfloat16>(g_wohi), *wolo = sym<__nv_bfloat16>(g_wolo);
    __nv_bfloat16 *w1hi = sym<__nv_bfloat16>(g_w1hi), *w1lo = sym<__nv_bfloat16>(g_w1lo);
    __nv_bfloat16 *w2hi = sym<__nv_bfloat16>(g_w2hi), *w2lo = sym<__nv_bfloat16>(g_w2lo);

    constexpr int SM128 = 2 * (2 * 128 * 80 + 2 * 128 * 80);  // 81920
    constexpr int SM64  = 2 * (2 * 128 * 80 + 2 * 64 * 80);   // 61440
    cudaFuncSetAttribute(gemm_mma<128,0>, cudaFuncAttributeMaxDynamicSharedMemorySize, SM128);
    cudaFuncSetAttribute(gemm_mma<128,1>, cudaFuncAttributeMaxDynamicSharedMemorySize, SM128);
    cudaFuncSetAttribute(gemm_mma<128,2>, cudaFuncAttributeMaxDynamicSharedMemorySize, SM128);
    cudaFuncSetAttribute(gemm_mma<128,4>, cudaFuncAttributeMaxDynamicSharedMemorySize, SM128);
    cudaFuncSetAttribute(gemm_mma<128,5>, cudaFuncAttributeMaxDynamicSharedMemorySize, SM128);
    cudaFuncSetAttribute(gemm_mma<64,3>,  cudaFuncAttributeMaxDynamicSharedMemorySize, SM64);

    const dim3 blk(256);

    // --- weight splits ---
    split_f32<<<(D_*D_ + 255) / 256, blk>>>(wq, wqhi, wqlo, D_*D_);
    split_f32<<<(D_*D_ + 255) / 256, blk>>>(wk, wkhi, wklo, D_*D_);
    split_f32<<<(D_*D_ + 255) / 256, blk>>>(wv, wvhi, wvlo, D_*D_);
    split_f32<<<(D_*D_ + 255) / 256, blk>>>(wo, wohi, wolo, D_*D_);
    split_f32<<<(DFF_*D_ + 255) / 256, blk>>>(w1, w1hi, w1lo, DFF_*D_);
    split_f32<<<(DFF_*D_ + 255) / 256, blk>>>(w2, w2hi, w2lo, DFF_*D_);

    // --- sublayer 1: pre-norm ---
    ln_kernel<<<S_, blk>>>(inputs, ln1_a, ln1_b, xhi, xlo);

    // --- Q, K projections; V projection with per-head transpose ---
    gemm_mma<128,1><<<dim3(D_/128, S_/128, 1), blk, SM128>>>(
        xhi, xlo, D_, 0, wqhi, wqlo, D_, 0, D_,
        nullptr, 0, D_, qhi, qlo, bq, nullptr, nullptr, 0.f);
    gemm_mma<128,1><<<dim3(D_/128, S_/128, 1), blk, SM128>>>(
        xhi, xlo, D_, 0, wkhi, wklo, D_, 0, D_,
        nullptr, 0, D_, khi, klo, bk, nullptr, nullptr, 0.f);
    gemm_mma<128,2><<<dim3(D_/128, S_/128, 1), blk, SM128>>>(
        xhi, xlo, D_, 0, wvhi, wvlo, D_, 0, D_,
        nullptr, 0, D_, vthi, vtlo, bv, nullptr, nullptr, 0.f);

    // --- scores per head: S x S, K=64, masked * 1/8 ---
    gemm_mma<128,0><<<dim3(S_/128, S_/128, H_), blk, SM128>>>(
        qhi, qlo, D_, 64, khi, klo, D_, 64, HD_,
        s, (long)S_ * S_, S_, nullptr, nullptr, nullptr, nullptr, mask, 0.125f);

    // --- entmax-1.5 -> split probs ---
    entmax_kernel<<<H_ * S_, blk>>>(s, phi, plo);

    // --- attended per head: S x 64, K=S ---
    gemm_mma<64,3><<<dim3(1, S_/128, H_), blk, SM64>>>(
        phi, plo, S_, (long)S_ * S_, vthi, vtlo, S_, (long)64 * S_, S_,
        nullptr, 0, D_, athi, atlo, nullptr, nullptr, nullptr, 0.f);

    // --- output projection + residual -> y (fp32) ---
    gemm_mma<128,4><<<dim3(D_/128, S_/128, 1), blk, SM128>>>(
        athi, atlo, D_, 0, wohi, wolo, D_, 0, D_,
        y, 0, D_, nullptr, nullptr, bo, inputs, nullptr, 0.f);

    // --- sublayer 2: pre-norm ---
    ln_kernel<<<S_, blk>>>(y, ln2_a, ln2_b, xhi, xlo);

    // --- FFN1: relu(x @ w1^T + b1) -> split ---
    gemm_mma<128,5><<<dim3(DFF_/128, S_/128, 1), blk, SM128>>>(
        xhi, xlo, D_, 0, w1hi, w1lo, D_, 0, D_,
        nullptr, 0, DFF_, h1hi, h1lo, b1, nullptr, nullptr, 0.f);

    // --- FFN2 + residual -> out ---
    gemm_mma<128,4><<<dim3(D_/128, S_/128, 1), blk, SM128>>>(
        h1hi, h1lo, DFF_, 0, w2hi, w2lo, DFF_, 0, DFF_,
        out, 0, D_, nullptr, nullptr, b2, y, nullptr, 0.f);
}

// round 4
// speedup vs baseline: 3.0600x; 1.3978x over previous
#include <cuda_runtime.h>
#include <cuda_fp16.h>
#include <cstdint>

#define S_   2048
#define D_   1024
#define H_   16
#define HD_  64
#define DFF_ 4096

// ---------------------------------------------------------------------------
// Device scratch (no runtime allocation allowed)
// ---------------------------------------------------------------------------
__device__ __align__(16) float  g_s  [(long)H_ * S_ * S_];   // fp32 scores
__device__ __align__(16) __half g_phi[(long)H_ * S_ * S_];   // probs hi
__device__ __align__(16) __half g_plo[(long)H_ * S_ * S_];   // probs lo
__device__ __align__(16) __half g_xhi[S_ * D_],  g_xlo[S_ * D_];
__device__ __align__(16) __half g_qhi[S_ * D_],  g_qlo[S_ * D_];
__device__ __align__(16) __half g_khi[S_ * D_];              // B-side: hi only
__device__ __align__(16) __half g_vthi[S_ * D_];             // [h][64][S], hi only
__device__ __align__(16) __half g_ahi[S_ * D_],  g_alo[S_ * D_];
__device__ __align__(16) float  g_y  [S_ * D_];
__device__ __align__(16) __half g_h1hi[S_ * DFF_], g_h1lo[S_ * DFF_];
__device__ __align__(16) __half g_wq[D_ * D_], g_wk[D_ * D_];
__device__ __align__(16) __half g_wv[D_ * D_], g_wo[D_ * D_];
__device__ __align__(16) __half g_w1[DFF_ * D_], g_w2[D_ * DFF_];

// ---------------------------------------------------------------------------
// PTX helpers (baseline PTX only)
// ---------------------------------------------------------------------------
__device__ __forceinline__ uint32_t smem_u32(const void* p) {
    uint32_t a;
    asm("{ .reg .u64 t; cvta.to.shared.u64 t, %1; cvt.u32.u64 %0, t; }"
        : "=r"(a) : "l"(p));
    return a;
}

#define CP16(dst, src) \
    asm volatile("cp.async.cg.shared.global [%0], [%1], 16;" \
                 :: "r"(dst), "l"(src))

#define LDSM4(r, addr) \
    asm volatile("ldmatrix.sync.aligned.m8n8.x4.shared.b16 {%0,%1,%2,%3}, [%4];" \
                 : "=r"((r)[0]), "=r"((r)[1]), "=r"((r)[2]), "=r"((r)[3]) \
                 : "r"(addr))

#define MMA16816(d, a, b) \
    asm volatile("mma.sync.aligned.m16n8k16.row.col.f32.f16.f16.f32 " \
                 "{%0,%1,%2,%3}, {%4,%5,%6,%7}, {%8,%9}, {%0,%1,%2,%3};" \
                 : "+f"((d)[0]), "+f"((d)[1]), "+f"((d)[2]), "+f"((d)[3]) \
                 : "r"((a)[0]), "r"((a)[1]), "r"((a)[2]), "r"((a)[3]), \
                   "r"((b)[0]), "r"((b)[1]))

__device__ __forceinline__ uint32_t pack2(__half a, __half b) {
    __half2 h; h.x = a; h.y = b;
    return *(uint32_t*)&h;
}

// pair split-store: col even -> 4B-aligned half2 stores
__device__ __forceinline__ void split2(float v0, float v1,
                                       __half* hi, __half* lo, long idx) {
    const __half h0 = __float2half_rn(v0), h1 = __float2half_rn(v1);
    const __half l0 = __float2half_rn(v0 - __half2float(h0));
    const __half l1 = __float2half_rn(v1 - __half2float(h1));
    *(uint32_t*)(hi + idx) = pack2(h0, h1);
    *(uint32_t*)(lo + idx) = pack2(l0, l1);
}

// ---------------------------------------------------------------------------
// All 6 weight matrices -> fp16 (hi only), one fused kernel, float4 vectorized
// segment sizes (float4 units): 4 x 262144, 2 x 1048576
// ---------------------------------------------------------------------------
__global__ __launch_bounds__(256)
void cvt_w(const float4* __restrict__ wq, const float4* __restrict__ wk,
           const float4* __restrict__ wv, const float4* __restrict__ wo,
           const float4* __restrict__ w1, const float4* __restrict__ w2,
           uint2* __restrict__ oq, uint2* __restrict__ ok,
           uint2* __restrict__ ov, uint2* __restrict__ oo,
           uint2* __restrict__ o1, uint2* __restrict__ o2)
{
    const int i = blockIdx.x * 256 + threadIdx.x;
    const float4* s; uint2* d; int off;
    if      (i <  262144) { s = wq; d = oq; off = i; }
    else if (i <  524288) { s = wk; d = ok; off = i -  262144; }
    else if (i <  786432) { s = wv; d = ov; off = i -  524288; }
    else if (i < 1048576) { s = wo; d = oo; off = i -  786432; }
    else if (i < 2097152) { s = w1; d = o1; off = i - 1048576; }
    else                  { s = w2; d = o2; off = i - 2097152; }
    const float4 v = s[off];
    const __half2 a = __floats2half2_rn(v.x, v.y);
    const __half2 b = __floats2half2_rn(v.z, v.w);
    d[off] = make_uint2(*(uint32_t*)&a, *(uint32_t*)&b);
}

// ---------------------------------------------------------------------------
// LayerNorm (ddof=1 std + 1e-6) -> split-fp16 output
// ---------------------------------------------------------------------------
__global__ __launch_bounds__(256)
void ln_kernel(const float* __restrict__ X, const float* __restrict__ ga,
               const float* __restrict__ gb,
               __half* __restrict__ OH, __half* __restrict__ OL)
{
    __shared__ float sm_s[8], sm_q[8];
    const long row = blockIdx.x;
    const int tid = threadIdx.x;
    const float4 v = ((const float4*)(X + row * D_))[tid];

    float s  = v.x + v.y + v.z + v.w;
    float sq = v.x*v.x + v.y*v.y + v.z*v.z + v.w*v.w;
    #pragma unroll
    for (int o = 16; o > 0; o >>= 1) {
        s  += __shfl_xor_sync(0xffffffffu, s,  o);
        sq += __shfl_xor_sync(0xffffffffu, sq, o);
    }
    if ((tid & 31) == 0) { sm_s[tid >> 5] = s; sm_q[tid >> 5] = sq; }
    __syncthreads();
    if (tid == 0) {
        float rs = 0.f, rq = 0.f;
        #pragma unroll
        for (int w = 0; w < 8; w++) { rs += sm_s[w]; rq += sm_q[w]; }
        sm_s[0] = rs; sm_q[0] = rq;
    }
    __syncthreads();
    const float mu  = sm_s[0] * (1.0f / D_);
    const float var = fmaxf((sm_q[0] - mu * mu * (float)D_) * (1.0f / (D_ - 1)), 0.0f);
    const float inv = 1.0f / (sqrtf(var) + 1e-6f);

    const float4 a4 = ((const float4*)ga)[tid];
    const float4 b4 = ((const float4*)gb)[tid];
    const float o0 = (v.x - mu) * inv * a4.x + b4.x;
    const float o1 = (v.y - mu) * inv * a4.y + b4.y;
    const float o2 = (v.z - mu) * inv * a4.z + b4.z;
    const float o3 = (v.w - mu) * inv * a4.w + b4.w;
    const long base = row * D_ + (long)tid * 4;
    split2(o0, o1, OH, OL, base);
    split2(o2, o3, OH, OL, base + 2);
}

// ---------------------------------------------------------------------------
// entmax-1.5 over one row of 2048 fp32 scores -> split-fp16 probs
// ---------------------------------------------------------------------------
__global__ __launch_bounds__(256)
void entmax_kernel(const float* __restrict__ SC,
                   __half* __restrict__ PH, __half* __restrict__ PL)
{
    __shared__ float sm[8];
    const long row = blockIdx.x;
    const float* p = SC + row * (long)S_;
    const int tid = threadIdx.x;

    float x[8];
    {
        const float4 v0 = ((const float4*)p)[tid * 2 + 0];
        const float4 v1 = ((const float4*)p)[tid * 2 + 1];
        x[0] = v0.x; x[1] = v0.y; x[2] = v0.z; x[3] = v0.w;
        x[4] = v1.x; x[5] = v1.y; x[6] = v1.z; x[7] = v1.w;
    }
    float mx = -3.4e38f;
    #pragma unroll
    for (int i = 0; i < 8; i++) { x[i] *= 0.5f; mx = fmaxf(mx, x[i]); }

    #pragma unroll
    for (int o = 16; o > 0; o >>= 1) mx = fmaxf(mx, __shfl_xor_sync(0xffffffffu, mx, o));
    if ((tid & 31) == 0) sm[tid >> 5] = mx;
    __syncthreads();
    if (tid == 0) {
        float r = sm[0];
        #pragma unroll
        for (int w = 1; w < 8; w++) r = fmaxf(r, sm[w]);
        sm[0] = r;
    }
    __syncthreads();
    mx = sm[0];
    __syncthreads();
    #pragma unroll
    for (int i = 0; i < 8; i++) x[i] -= mx;

    float lo = -1.0f, hi = 0.0f;
    for (int it = 0; it < 26; it++) {
        const float mid = 0.5f * (lo + hi);
        float s = 0.f;
        #pragma unroll
        for (int i = 0; i < 8; i++) {
            const float t = fmaxf(x[i] - mid, 0.f);
            s = fmaf(t, t, s);
        }
        #pragma unroll
        for (int o = 16; o > 0; o >>= 1) s += __shfl_xor_sync(0xffffffffu, s, o);
        if ((tid & 31) == 0) sm[tid >> 5] = s;
        __syncthreads();
        if (tid == 0) {
            float r = 0.f;
            #pragma unroll
            for (int w = 0; w < 8; w++) r += sm[w];
            sm[0] = r;
        }
        __syncthreads();
        s = sm[0];
        __syncthreads();
        if (s >= 1.0f) lo = mid; else hi = mid;
    }
    const float tau = 0.5f * (lo + hi);

    __half hb[8], lb[8];
    #pragma unroll
    for (int i = 0; i < 8; i++) {
        const float t = fmaxf(x[i] - tau, 0.f);
        const float o = t * t;
        hb[i] = __float2half_rn(o);
        lb[i] = __float2half_rn(o - __half2float(hb[i]));
    }
    const long base = row * (long)S_ + (long)tid * 8;
    *(uint4*)(PH + base) = *(const uint4*)hb;
    *(uint4*)(PL + base) = *(const uint4*)lb;
}

// ---------------------------------------------------------------------------
// Warp-MMA fp16x2 GEMM.  C[m,n] = sum_k A[m,k]*B[n,k]  (K-major both)
// acc += Ah*Bh + Al*Bh   (A split into hi+lo, B truncated to hi)
// CTA tile: 128 x BN x 32, 8 warps, 3-stage cp.async pipeline.
// MODE: 0 scores (mask+scale -> fp32), 1 bias -> split, 2 bias -> hi-only V^T,
//       3 plain -> split att (col += z*64), 4 bias+resid -> fp32,
//       5 bias+relu -> split, 6 bias -> hi only
// ---------------------------------------------------------------------------
template<int BN, int MODE>
__global__ __launch_bounds__(256, 2)
void gemm_mma(const __half* __restrict__ Ahi, const __half* __restrict__ Alo,
              int lda, long zsA,
              const __half* __restrict__ Bhi, int ldb, long zsB,
              int K,
              float* __restrict__ Cf, long zsC, int ldc,
              __half* __restrict__ Chi, __half* __restrict__ Clo,
              const float* __restrict__ bias, const float* __restrict__ resid,
              const int* __restrict__ mask, float alpha)
{
    constexpr int BM = 128, BK = 32;
    constexpr int WARPS_N = (BN == 128) ? 4 : 2;
    constexpr int WARPS_M = 8 / WARPS_N;
    constexpr int WM = BM / WARPS_M;
    constexpr int WN = BN / WARPS_N;        // 32
    constexpr int MI = WM / 16;             // 4 or 2
    constexpr int NJ = WN / 8;              // 4
    constexpr int LDSB   = 80;
    constexpr int ABYTES = BM * LDSB;       // 10240
    constexpr int BBYTES = BN * LDSB;
    constexpr int STAGE  = 2 * ABYTES + BBYTES;

    extern __shared__ char smem[];
    const uint32_t sb = smem_u32(smem);

    const int tid  = threadIdx.x;
    const int wid  = tid >> 5;
    const int lane = tid & 31;
    const int z    = blockIdx.z;
    const int m0   = blockIdx.y * BM;
    const int n0   = blockIdx.x * BN;
    const int wtm  = (wid / WARPS_N) * WM;
    const int wtn  = (wid % WARPS_N) * WN;

    const __half* ah = Ahi + (long)z * zsA + (long)m0 * lda;
    const __half* al = Alo + (long)z * zsA + (long)m0 * lda;
    const __half* bh = Bhi + (long)z * zsB + (long)n0 * ldb;

    float acc[MI][NJ][4];
    #pragma unroll
    for (int i = 0; i < MI; i++)
        #pragma unroll
        for (int j = 0; j < NJ; j++)
            #pragma unroll
            for (int r = 0; r < 4; r++) acc[i][j][r] = 0.f;

    const int nc = K / BK;

    auto load_stage = [&](int buf, int c) {
        const uint32_t base = sb + buf * STAGE;
        const int k0 = c * BK;
        #pragma unroll
        for (int it = 0; it < (BM * 4) / 256; it++) {
            const int ci = tid + it * 256;
            const int r = ci >> 2, q = ci & 3;
            const uint32_t d = base + r * LDSB + q * 16;
            CP16(d,          ah + (long)r * lda + k0 + q * 8);
            CP16(d + ABYTES, al + (long)r * lda + k0 + q * 8);
        }
        #pragma unroll
        for (int it = 0; it < (BN * 4) / 256; it++) {
            const int ci = tid + it * 256;
            const int r = ci >> 2, q = ci & 3;
            CP16(base + 2 * ABYTES + r * LDSB + q * 16,
                 bh + (long)r * ldb + k0 + q * 8);
        }
        asm volatile("cp.async.commit_group;");
    };

    load_stage(0, 0);
    if (nc > 1) load_stage(1, 1);

    for (int c = 0; c < nc; c++) {
        if (c + 2 < nc) {
            load_stage((c + 2) % 3, c + 2);
            asm volatile("cp.async.wait_group 2;");
        } else if (c + 1 < nc) {
            asm volatile("cp.async.wait_group 1;");
        } else {
            asm volatile("cp.async.wait_group 0;");
        }
        __syncthreads();

        const uint32_t base = sb + (c % 3) * STAGE;
        #pragma unroll
        for (int ks = 0; ks < 2; ks++) {
            uint32_t afh[MI][4], afl[MI][4];
            #pragma unroll
            for (int i = 0; i < MI; i++) {
                const int row = wtm + i * 16 + (lane & 15);
                const int kc  = ks * 16 + ((lane >> 4) << 3);
                const uint32_t ad = base + row * LDSB + kc * 2;
                LDSM4(afh[i], ad);
                LDSM4(afl[i], ad + ABYTES);
            }
            uint32_t bfh[NJ][2];
            #pragma unroll
            for (int jp = 0; jp < NJ / 2; jp++) {
                const int nrow = wtn + jp * 16 + (lane & 7) + ((lane & 16) ? 8 : 0);
                const int kc   = ks * 16 + ((lane & 8) ? 8 : 0);
                const uint32_t bd = base + 2 * ABYTES + nrow * LDSB + kc * 2;
                uint32_t t[4];
                LDSM4(t, bd);
                bfh[2*jp][0]   = t[0]; bfh[2*jp][1]   = t[1];
                bfh[2*jp+1][0] = t[2]; bfh[2*jp+1][1] = t[3];
            }
            #pragma unroll
            for (int i = 0; i < MI; i++)
                #pragma unroll
                for (int j = 0; j < NJ; j++) {
                    MMA16816(acc[i][j], afh[i], bfh[j]);
                    MMA16816(acc[i][j], afl[i], bfh[j]);
                }
        }
        __syncthreads();
    }

    // ---- epilogue (paired stores: r={0,1} and r={2,3} share a row) ----
    #pragma unroll
    for (int i = 0; i < MI; i++)
        #pragma unroll
        for (int j = 0; j < NJ; j++)
            #pragma unroll
            for (int h = 0; h < 2; h++) {
                const int row = m0 + wtm + i * 16 + (lane >> 2) + h * 8;
                const int col = n0 + wtn + j * 8 + (lane & 3) * 2;
                float v0 = acc[i][j][2*h], v1 = acc[i][j][2*h+1];
                if (MODE == 0) {
                    v0 = mask[col]     ? v0 * alpha : -1e9f;
                    v1 = mask[col + 1] ? v1 * alpha : -1e9f;
                    *(float2*)(Cf + (long)z * zsC + (long)row * ldc + col)
                        = make_float2(v0, v1);
                } else if (MODE == 1 || MODE == 5) {
                    const float2 b2 = *(const float2*)(bias + col);
                    v0 += b2.x; v1 += b2.y;
                    if (MODE == 5) { v0 = fmaxf(v0, 0.f); v1 = fmaxf(v1, 0.f); }
                    split2(v0, v1, Chi, Clo, (long)row * ldc + col);
                } else if (MODE == 6) {
                    const float2 b2 = *(const float2*)(bias + col);
                    *(uint32_t*)(Chi + (long)row * ldc + col)
                        = pack2(__float2half_rn(v0 + b2.x), __float2half_rn(v1 + b2.y));
                } else if (MODE == 2) {
                    const float2 b2 = *(const float2*)(bias + col);
                    Chi[(long)col * S_ + row]       = __float2half_rn(v0 + b2.x);
                    Chi[(long)(col + 1) * S_ + row] = __float2half_rn(v1 + b2.y);
                } else if (MODE == 3) {
                    split2(v0, v1, Chi, Clo, (long)row * ldc + z * 64 + col);
                } else {  // MODE 4
                    const long idx = (long)row * ldc + col;
                    const float2 b2 = *(const float2*)(bias + col);
                    const float2 r2 = *(const float2*)(resid + idx);
                    *(float2*)(Cf + idx) = make_float2(v0 + b2.x + r2.x,
                                                       v1 + b2.y + r2.y);
                }
            }
}

// ---------------------------------------------------------------------------
// Launch
// ---------------------------------------------------------------------------
template<typename T>
static T* sym(const void* s) {
    void* p = nullptr;
    cudaGetSymbolAddress(&p, s);
    return (T*)p;
}

extern "C" void kernel_launch(void* const* d_in, const int* in_sizes, int n_in,
                              void* d_out, int out_size)
{
    const float* inputs = (const float*)d_in[0];
    const int*   mask   = (const int*)  d_in[1];
    const float* wq = (const float*)d_in[2];  const float* bq = (const float*)d_in[3];
    const float* wk = (const float*)d_in[4];  const float* bk = (const float*)d_in[5];
    const float* wv = (const float*)d_in[6];  const float* bv = (const float*)d_in[7];
    const float* wo = (const float*)d_in[8];  const float* bo = (const float*)d_in[9];
    const float* ln1_a = (const float*)d_in[10]; const float* ln1_b = (const float*)d_in[11];
    const float* w1 = (const float*)d_in[12]; const float* b1 = (const float*)d_in[13];
    const float* w2 = (const float*)d_in[14]; const float* b2 = (const float*)d_in[15];
    const float* ln2_a = (const float*)d_in[16]; const float* ln2_b = (const float*)d_in[17];
    float* out = (float*)d_out;

    float* s    = sym<float>(g_s);
    __half *phi = sym<__half>(g_phi), *plo = sym<__half>(g_plo);
    __half *xhi = sym<__half>(g_xhi), *xlo = sym<__half>(g_xlo);
    __half *qhi = sym<__half>(g_qhi), *qlo = sym<__half>(g_qlo);
    __half *khi = sym<__half>(g_khi);
    __half *vthi = sym<__half>(g_vthi);
    __half *athi = sym<__half>(g_ahi), *atlo = sym<__half>(g_alo);
    float* y = sym<float>(g_y);
    __half *h1hi = sym<__half>(g_h1hi), *h1lo = sym<__half>(g_h1lo);
    __half *wqh = sym<__half>(g_wq), *wkh = sym<__half>(g_wk);
    __half *wvh = sym<__half>(g_wv), *woh = sym<__half>(g_wo);
    __half *w1h = sym<__half>(g_w1), *w2h = sym<__half>(g_w2);

    constexpr int ST128 = 2 * 128 * 80 + 128 * 80;  // 30720
    constexpr int ST64  = 2 * 128 * 80 + 64 * 80;   // 25600
    constexpr int SM128 = 3 * ST128;                 // 92160
    constexpr int SM64  = 3 * ST64;                  // 76800
    cudaFuncSetAttribute(gemm_mma<128,0>, cudaFuncAttributeMaxDynamicSharedMemorySize, SM128);
    cudaFuncSetAttribute(gemm_mma<64,1>,  cudaFuncAttributeMaxDynamicSharedMemorySize, SM64);
    cudaFuncSetAttribute(gemm_mma<64,2>,  cudaFuncAttributeMaxDynamicSharedMemorySize, SM64);
    cudaFuncSetAttribute(gemm_mma<64,3>,  cudaFuncAttributeMaxDynamicSharedMemorySize, SM64);
    cudaFuncSetAttribute(gemm_mma<64,4>,  cudaFuncAttributeMaxDynamicSharedMemorySize, SM64);
    cudaFuncSetAttribute(gemm_mma<64,5>,  cudaFuncAttributeMaxDynamicSharedMemorySize, SM64);
    cudaFuncSetAttribute(gemm_mma<64,6>,  cudaFuncAttributeMaxDynamicSharedMemorySize, SM64);

    const dim3 blk(256);

    // --- all weights -> fp16 in one kernel ---
    cvt_w<<<12288, blk>>>((const float4*)wq, (const float4*)wk, (const float4*)wv,
                          (const float4*)wo, (const float4*)w1, (const float4*)w2,
                          (uint2*)wqh, (uint2*)wkh, (uint2*)wvh,
                          (uint2*)woh, (uint2*)w1h, (uint2*)w2h);

    // --- sublayer 1: pre-norm ---
    ln_kernel<<<S_, blk>>>(inputs, ln1_a, ln1_b, xhi, xlo);

    // --- Q (split), K (hi only), V (hi only, per-head transposed) ---
    gemm_mma<64,1><<<dim3(D_/64, S_/128, 1), blk, SM64>>>(
        xhi, xlo, D_, 0, wqh, D_, 0, D_,
        nullptr, 0, D_, qhi, qlo, bq, nullptr, nullptr, 0.f);
    gemm_mma<64,6><<<dim3(D_/64, S_/128, 1), blk, SM64>>>(
        xhi, xlo, D_, 0, wkh, D_, 0, D_,
        nullptr, 0, D_, khi, nullptr, bk, nullptr, nullptr, 0.f);
    gemm_mma<64,2><<<dim3(D_/64, S_/128, 1), blk, SM64>>>(
        xhi, xlo, D_, 0, wvh, D_, 0, D_,
        nullptr, 0, D_, vthi, nullptr, bv, nullptr, nullptr, 0.f);

    // --- scores per head: S x S, K=64, masked * 1/8 ---
    gemm_mma<128,0><<<dim3(S_/128, S_/128, H_), blk, SM128>>>(
        qhi, qlo, D_, 64, khi, D_, 64, HD_,
        s, (long)S_ * S_, S_, nullptr, nullptr, nullptr, nullptr, mask, 0.125f);

    // --- entmax-1.5 -> split probs ---
    entmax_kernel<<<H_ * S_, blk>>>(s, phi, plo);

    // --- attended per head: S x 64, K=S ---
    gemm_mma<64,3><<<dim3(1, S_/128, H_), blk, SM64>>>(
        phi, plo, S_, (long)S_ * S_, vthi, S_, (long)64 * S_, S_,
        nullptr, 0, D_, athi, atlo, nullptr, nullptr, nullptr, 0.f);

    // --- output projection + residual -> y (fp32) ---
    gemm_mma<64,4><<<dim3(D_/64, S_/128, 1), blk, SM64>>>(
        athi, atlo, D_, 0, woh, D_, 0, D_,
        y, 0, D_, nullptr, nullptr, bo, inputs, nullptr, 0.f);

    // --- sublayer 2: pre-norm ---
    ln_kernel<<<S_, blk>>>(y, ln2_a, ln2_b, xhi, xlo);

    // --- FFN1: relu(x @ w1^T + b1) -> split ---
    gemm_mma<64,5><<<dim3(DFF_/64, S_/128, 1), blk, SM64>>>(
        xhi, xlo, D_, 0, w1h, D_, 0, D_,
        nullptr, 0, DFF_, h1hi, h1lo, b1, nullptr, nullptr, 0.f);

    // --- FFN2 + residual -> out ---
    gemm_mma<64,4><<<dim3(D_/64, S_/128, 1), blk, SM64>>>(
        h1hi, h1lo, DFF_, 0, w2h, DFF_, 0, DFF_,
        out, 0, D_, nullptr, nullptr, b2, y, nullptr, 0.f);
}

// round 5
// speedup vs baseline: 3.3367x; 1.0904x over previous
#include <cuda_runtime.h>
#include <cuda_fp16.h>
#include <cstdint>

#define S_   2048
#define D_   1024
#define H_   16
#define HD_  64
#define DFF_ 4096

// ---------------------------------------------------------------------------
// Device scratch (no runtime allocation allowed)
// ---------------------------------------------------------------------------
__device__ __align__(16) float  g_s  [(long)H_ * S_ * S_];   // fp32 scores
__device__ __align__(16) __half g_phi[(long)H_ * S_ * S_];   // probs (hi only)
__device__ __align__(16) __half g_xhi[S_ * D_],  g_xlo[S_ * D_];
__device__ __align__(16) __half g_qhi[S_ * D_],  g_qlo[S_ * D_];
__device__ __align__(16) __half g_khi[S_ * D_];              // hi only
__device__ __align__(16) __half g_vthi[S_ * D_];             // [h][64][S], hi only
__device__ __align__(16) __half g_ahi[S_ * D_],  g_alo[S_ * D_];
__device__ __align__(16) float  g_y  [S_ * D_];
__device__ __align__(16) __half g_h1hi[S_ * DFF_], g_h1lo[S_ * DFF_];
__device__ __align__(16) __half g_wq[D_ * D_], g_wk[D_ * D_];
__device__ __align__(16) __half g_wv[D_ * D_], g_wo[D_ * D_];
__device__ __align__(16) __half g_w1[DFF_ * D_], g_w2[D_ * DFF_];

// ---------------------------------------------------------------------------
// PTX helpers (baseline PTX only)
// ---------------------------------------------------------------------------
__device__ __forceinline__ uint32_t smem_u32(const void* p) {
    uint32_t a;
    asm("{ .reg .u64 t; cvta.to.shared.u64 t, %1; cvt.u32.u64 %0, t; }"
        : "=r"(a) : "l"(p));
    return a;
}

#define CP16(dst, src) \
    asm volatile("cp.async.cg.shared.global [%0], [%1], 16;" \
                 :: "r"(dst), "l"(src))

#define LDSM4(r, addr) \
    asm volatile("ldmatrix.sync.aligned.m8n8.x4.shared.b16 {%0,%1,%2,%3}, [%4];" \
                 : "=r"((r)[0]), "=r"((r)[1]), "=r"((r)[2]), "=r"((r)[3]) \
                 : "r"(addr))

#define MMA16816(d, a, b) \
    asm volatile("mma.sync.aligned.m16n8k16.row.col.f32.f16.f16.f32 " \
                 "{%0,%1,%2,%3}, {%4,%5,%6,%7}, {%8,%9}, {%0,%1,%2,%3};" \
                 : "+f"((d)[0]), "+f"((d)[1]), "+f"((d)[2]), "+f"((d)[3]) \
                 : "r"((a)[0]), "r"((a)[1]), "r"((a)[2]), "r"((a)[3]), \
                   "r"((b)[0]), "r"((b)[1]))

__device__ __forceinline__ uint32_t pack2(__half a, __half b) {
    __half2 h; h.x = a; h.y = b;
    return *(uint32_t*)&h;
}

__device__ __forceinline__ void split2(float v0, float v1,
                                       __half* hi, __half* lo, long idx) {
    const __half h0 = __float2half_rn(v0), h1 = __float2half_rn(v1);
    const __half l0 = __float2half_rn(v0 - __half2float(h0));
    const __half l1 = __float2half_rn(v1 - __half2float(h1));
    *(uint32_t*)(hi + idx) = pack2(h0, h1);
    *(uint32_t*)(lo + idx) = pack2(l0, l1);
}

// ---------------------------------------------------------------------------
// All 6 weight matrices -> fp16 (hi only), one fused kernel
// ---------------------------------------------------------------------------
__global__ __launch_bounds__(256)
void cvt_w(const float4* __restrict__ wq, const float4* __restrict__ wk,
           const float4* __restrict__ wv, const float4* __restrict__ wo,
           const float4* __restrict__ w1, const float4* __restrict__ w2,
           uint2* __restrict__ oq, uint2* __restrict__ ok,
           uint2* __restrict__ ov, uint2* __restrict__ oo,
           uint2* __restrict__ o1, uint2* __restrict__ o2)
{
    const int i = blockIdx.x * 256 + threadIdx.x;
    const float4* s; uint2* d; int off;
    if      (i <  262144) { s = wq; d = oq; off = i; }
    else if (i <  524288) { s = wk; d = ok; off = i -  262144; }
    else if (i <  786432) { s = wv; d = ov; off = i -  524288; }
    else if (i < 1048576) { s = wo; d = oo; off = i -  786432; }
    else if (i < 2097152) { s = w1; d = o1; off = i - 1048576; }
    else                  { s = w2; d = o2; off = i - 2097152; }
    const float4 v = s[off];
    const __half2 a = __floats2half2_rn(v.x, v.y);
    const __half2 b = __floats2half2_rn(v.z, v.w);
    d[off] = make_uint2(*(uint32_t*)&a, *(uint32_t*)&b);
}

// ---------------------------------------------------------------------------
// LayerNorm (ddof=1 std + 1e-6) -> split-fp16 output
// ---------------------------------------------------------------------------
__global__ __launch_bounds__(256)
void ln_kernel(const float* __restrict__ X, const float* __restrict__ ga,
               const float* __restrict__ gb,
               __half* __restrict__ OH, __half* __restrict__ OL)
{
    __shared__ float sm_s[8], sm_q[8];
    const long row = blockIdx.x;
    const int tid = threadIdx.x;
    const float4 v = ((const float4*)(X + row * D_))[tid];

    float s  = v.x + v.y + v.z + v.w;
    float sq = v.x*v.x + v.y*v.y + v.z*v.z + v.w*v.w;
    #pragma unroll
    for (int o = 16; o > 0; o >>= 1) {
        s  += __shfl_xor_sync(0xffffffffu, s,  o);
        sq += __shfl_xor_sync(0xffffffffu, sq, o);
    }
    if ((tid & 31) == 0) { sm_s[tid >> 5] = s; sm_q[tid >> 5] = sq; }
    __syncthreads();
    if (tid == 0) {
        float rs = 0.f, rq = 0.f;
        #pragma unroll
        for (int w = 0; w < 8; w++) { rs += sm_s[w]; rq += sm_q[w]; }
        sm_s[0] = rs; sm_q[0] = rq;
    }
    __syncthreads();
    const float mu  = sm_s[0] * (1.0f / D_);
    const float var = fmaxf((sm_q[0] - mu * mu * (float)D_) * (1.0f / (D_ - 1)), 0.0f);
    const float inv = 1.0f / (sqrtf(var) + 1e-6f);

    const float4 a4 = ((const float4*)ga)[tid];
    const float4 b4 = ((const float4*)gb)[tid];
    const float o0 = (v.x - mu) * inv * a4.x + b4.x;
    const float o1 = (v.y - mu) * inv * a4.y + b4.y;
    const float o2 = (v.z - mu) * inv * a4.z + b4.z;
    const float o3 = (v.w - mu) * inv * a4.w + b4.w;
    const long base = row * D_ + (long)tid * 4;
    split2(o0, o1, OH, OL, base);
    split2(o2, o3, OH, OL, base + 2);
}

// ---------------------------------------------------------------------------
// entmax-1.5, Newton iteration.  f(tau)=sum relu(x-tau)^2 is convex and
// strictly decreasing; from tau0=-1 (f>=1) Newton converges monotonically,
// quadratically.  12 iterations -> fp32-exact tau.
// probs written fp16 (hi only).
// ---------------------------------------------------------------------------
__global__ __launch_bounds__(256)
void entmax_kernel(const float* __restrict__ SC, __half* __restrict__ PH)
{
    __shared__ float smf[2][8], smg[2][8];
    const long row = blockIdx.x;
    const float* p = SC + row * (long)S_;
    const int tid = threadIdx.x;

    float x[8];
    {
        const float4 v0 = ((const float4*)p)[tid * 2 + 0];
        const float4 v1 = ((const float4*)p)[tid * 2 + 1];
        x[0] = v0.x; x[1] = v0.y; x[2] = v0.z; x[3] = v0.w;
        x[4] = v1.x; x[5] = v1.y; x[6] = v1.z; x[7] = v1.w;
    }
    float mx = -3.4e38f;
    #pragma unroll
    for (int i = 0; i < 8; i++) { x[i] *= 0.5f; mx = fmaxf(mx, x[i]); }

    #pragma unroll
    for (int o = 16; o > 0; o >>= 1) mx = fmaxf(mx, __shfl_xor_sync(0xffffffffu, mx, o));
    if ((tid & 31) == 0) smf[0][tid >> 5] = mx;
    __syncthreads();
    {
        float r = smf[0][0];
        #pragma unroll
        for (int w = 1; w < 8; w++) r = fmaxf(r, smf[0][w]);
        mx = r;
    }
    __syncthreads();
    #pragma unroll
    for (int i = 0; i < 8; i++) x[i] -= mx;

    float tau = -1.0f;
    #pragma unroll 1
    for (int it = 0; it < 12; it++) {
        float f = 0.f, g = 0.f;
        #pragma unroll
        for (int i = 0; i < 8; i++) {
            const float t = fmaxf(x[i] - tau, 0.f);
            f = fmaf(t, t, f);
            g += t;
        }
        #pragma unroll
        for (int o = 16; o > 0; o >>= 1) {
            f += __shfl_xor_sync(0xffffffffu, f, o);
            g += __shfl_xor_sync(0xffffffffu, g, o);
        }
        const int buf = it & 1;
        if ((tid & 31) == 0) { smf[buf][tid >> 5] = f; smg[buf][tid >> 5] = g; }
        __syncthreads();
        float rf = 0.f, rg = 0.f;
        #pragma unroll
        for (int w = 0; w < 8; w++) { rf += smf[buf][w]; rg += smg[buf][w]; }
        tau += (rf - 1.0f) / (2.0f * rg);
    }

    __half hb[8];
    #pragma unroll
    for (int i = 0; i < 8; i++) {
        const float t = fmaxf(x[i] - tau, 0.f);
        hb[i] = __float2half_rn(t * t);
    }
    *(uint4*)(PH + row * (long)S_ + (long)tid * 8) = *(const uint4*)hb;
}

// ---------------------------------------------------------------------------
// Warp-MMA fp16 GEMM.  C[m,n] = sum_k A[m,k]*B[n,k]  (K-major both)
// ASPLIT: acc += Ah*Bh + Al*Bh  else acc += Ah*Bh.
// BM=128 fixed; warp tile WM x WN; 3-stage cp.async pipeline.
// MODE: 0 scores (mask+scale -> fp32), 1 bias -> split, 2 bias -> hi V^T,
//       3 plain -> split att (col += z*64), 4 bias+resid -> fp32,
//       5 bias+relu -> split, 6 bias -> hi only
// ---------------------------------------------------------------------------
template<int BN, int WM, int WN, int MODE, bool ASPLIT>
__global__ __launch_bounds__((128 / WM) * (BN / WN) * 32, 2)
void gemm_mma(const __half* __restrict__ Ahi, const __half* __restrict__ Alo,
              int lda, long zsA,
              const __half* __restrict__ Bhi, int ldb, long zsB,
              int K,
              float* __restrict__ Cf, long zsC, int ldc,
              __half* __restrict__ Chi, __half* __restrict__ Clo,
              const float* __restrict__ bias, const float* __restrict__ resid,
              const int* __restrict__ mask, float alpha)
{
    constexpr int BM = 128, BK = 32;
    constexpr int WARPS_M = BM / WM, WARPS_N = BN / WN;
    constexpr int THREADS = WARPS_M * WARPS_N * 32;
    constexpr int MI = WM / 16, NJ = WN / 8;
    constexpr int LDSB   = 80;
    constexpr int ABYTES = BM * LDSB;
    constexpr int BBYTES = BN * LDSB;
    constexpr int ASZ    = ASPLIT ? 2 * ABYTES : ABYTES;
    constexpr int STAGE  = ASZ + BBYTES;

    extern __shared__ char smem[];
    const uint32_t sb = smem_u32(smem);

    const int tid  = threadIdx.x;
    const int wid  = tid >> 5;
    const int lane = tid & 31;
    const int z    = blockIdx.z;
    const int m0   = blockIdx.y * BM;
    const int n0   = blockIdx.x * BN;
    const int wtm  = (wid / WARPS_N) * WM;
    const int wtn  = (wid % WARPS_N) * WN;

    const __half* ah = Ahi + (long)z * zsA + (long)m0 * lda;
    const __half* al = ASPLIT ? (Alo + (long)z * zsA + (long)m0 * lda) : nullptr;
    const __half* bh = Bhi + (long)z * zsB + (long)n0 * ldb;

    float acc[MI][NJ][4];
    #pragma unroll
    for (int i = 0; i < MI; i++)
        #pragma unroll
        for (int j = 0; j < NJ; j++)
            #pragma unroll
            for (int r = 0; r < 4; r++) acc[i][j][r] = 0.f;

    const int nc = K / BK;

    auto load_stage = [&](int buf, int c) {
        const uint32_t base = sb + buf * STAGE;
        const int k0 = c * BK;
        #pragma unroll
        for (int it = 0; it < (BM * 4) / THREADS; it++) {
            const int ci = tid + it * THREADS;
            const int r = ci >> 2, q = ci & 3;
            const uint32_t d = base + r * LDSB + q * 16;
            CP16(d, ah + (long)r * lda + k0 + q * 8);
            if (ASPLIT)
                CP16(d + ABYTES, al + (long)r * lda + k0 + q * 8);
        }
        #pragma unroll
        for (int it = 0; it < (BN * 4) / THREADS; it++) {
            const int ci = tid + it * THREADS;
            const int r = ci >> 2, q = ci & 3;
            CP16(base + ASZ + r * LDSB + q * 16,
                 bh + (long)r * ldb + k0 + q * 8);
        }
        asm volatile("cp.async.commit_group;");
    };

    load_stage(0, 0);
    if (nc > 1) load_stage(1, 1);

    for (int c = 0; c < nc; c++) {
        if (c + 2 < nc) {
            load_stage((c + 2) % 3, c + 2);
            asm volatile("cp.async.wait_group 2;");
        } else if (c + 1 < nc) {
            asm volatile("cp.async.wait_group 1;");
        } else {
            asm volatile("cp.async.wait_group 0;");
        }
        __syncthreads();

        const uint32_t base = sb + (c % 3) * STAGE;
        #pragma unroll
        for (int ks = 0; ks < 2; ks++) {
            uint32_t afh[MI][4], afl[MI][4];
            #pragma unroll
            for (int i = 0; i < MI; i++) {
                const int row = wtm + i * 16 + (lane & 15);
                const int kc  = ks * 16 + ((lane >> 4) << 3);
                const uint32_t ad = base + row * LDSB + kc * 2;
                LDSM4(afh[i], ad);
                if (ASPLIT) LDSM4(afl[i], ad + ABYTES);
            }
            uint32_t bfh[NJ][2];
            #pragma unroll
            for (int jp = 0; jp < NJ / 2; jp++) {
                const int nrow = wtn + jp * 16 + (lane & 7) + ((lane & 16) ? 8 : 0);
                const int kc   = ks * 16 + ((lane & 8) ? 8 : 0);
                uint32_t t[4];
                LDSM4(t, base + ASZ + nrow * LDSB + kc * 2);
                bfh[2*jp][0]   = t[0]; bfh[2*jp][1]   = t[1];
                bfh[2*jp+1][0] = t[2]; bfh[2*jp+1][1] = t[3];
            }
            #pragma unroll
            for (int i = 0; i < MI; i++)
                #pragma unroll
                for (int j = 0; j < NJ; j++) {
                    MMA16816(acc[i][j], afh[i], bfh[j]);
                    if (ASPLIT) MMA16816(acc[i][j], afl[i], bfh[j]);
                }
        }
        __syncthreads();
    }

    // ---- epilogue (paired stores) ----
    #pragma unroll
    for (int i = 0; i < MI; i++)
        #pragma unroll
        for (int j = 0; j < NJ; j++)
            #pragma unroll
            for (int h = 0; h < 2; h++) {
                const int row = m0 + wtm + i * 16 + (lane >> 2) + h * 8;
                const int col = n0 + wtn + j * 8 + (lane & 3) * 2;
                float v0 = acc[i][j][2*h], v1 = acc[i][j][2*h+1];
                if (MODE == 0) {
                    v0 = mask[col]     ? v0 * alpha : -1e9f;
                    v1 = mask[col + 1] ? v1 * alpha : -1e9f;
                    *(float2*)(Cf + (long)z * zsC + (long)row * ldc + col)
                        = make_float2(v0, v1);
                } else if (MODE == 1 || MODE == 5) {
                    const float2 b2 = *(const float2*)(bias + col);
                    v0 += b2.x; v1 += b2.y;
                    if (MODE == 5) { v0 = fmaxf(v0, 0.f); v1 = fmaxf(v1, 0.f); }
                    split2(v0, v1, Chi, Clo, (long)row * ldc + col);
                } else if (MODE == 6) {
                    const float2 b2 = *(const float2*)(bias + col);
                    *(uint32_t*)(Chi + (long)row * ldc + col)
                        = pack2(__float2half_rn(v0 + b2.x), __float2half_rn(v1 + b2.y));
                } else if (MODE == 2) {
                    const float2 b2 = *(const float2*)(bias + col);
                    Chi[(long)col * S_ + row]       = __float2half_rn(v0 + b2.x);
                    Chi[(long)(col + 1) * S_ + row] = __float2half_rn(v1 + b2.y);
                } else if (MODE == 3) {
                    split2(v0, v1, Chi, Clo, (long)row * ldc + z * 64 + col);
                } else {  // MODE 4
                    const long idx = (long)row * ldc + col;
                    const float2 b2 = *(const float2*)(bias + col);
                    const float2 r2 = *(const float2*)(resid + idx);
                    *(float2*)(Cf + idx) = make_float2(v0 + b2.x + r2.x,
                                                       v1 + b2.y + r2.y);
                }
            }
}

// ---------------------------------------------------------------------------
// Launch
// ---------------------------------------------------------------------------
template<typename T>
static T* sym(const void* s) {
    void* p = nullptr;
    cudaGetSymbolAddress(&p, s);
    return (T*)p;
}

extern "C" void kernel_launch(void* const* d_in, const int* in_sizes, int n_in,
                              void* d_out, int out_size)
{
    const float* inputs = (const float*)d_in[0];
    const int*   mask   = (const int*)  d_in[1];
    const float* wq = (const float*)d_in[2];  const float* bq = (const float*)d_in[3];
    const float* wk = (const float*)d_in[4];  const float* bk = (const float*)d_in[5];
    const float* wv = (const float*)d_in[6];  const float* bv = (const float*)d_in[7];
    const float* wo = (const float*)d_in[8];  const float* bo = (const float*)d_in[9];
    const float* ln1_a = (const float*)d_in[10]; const float* ln1_b = (const float*)d_in[11];
    const float* w1 = (const float*)d_in[12]; const float* b1 = (const float*)d_in[13];
    const float* w2 = (const float*)d_in[14]; const float* b2 = (const float*)d_in[15];
    const float* ln2_a = (const float*)d_in[16]; const float* ln2_b = (const float*)d_in[17];
    float* out = (float*)d_out;

    float* s    = sym<float>(g_s);
    __half *phi = sym<__half>(g_phi);
    __half *xhi = sym<__half>(g_xhi), *xlo = sym<__half>(g_xlo);
    __half *qhi = sym<__half>(g_qhi), *qlo = sym<__half>(g_qlo);
    __half *khi = sym<__half>(g_khi);
    __half *vthi = sym<__half>(g_vthi);
    __half *athi = sym<__half>(g_ahi), *atlo = sym<__half>(g_alo);
    float* y = sym<float>(g_y);
    __half *h1hi = sym<__half>(g_h1hi), *h1lo = sym<__half>(g_h1lo);
    __half *wqh = sym<__half>(g_wq), *wkh = sym<__half>(g_wk);
    __half *wvh = sym<__half>(g_wv), *woh = sym<__half>(g_wo);
    __half *w1h = sym<__half>(g_w1), *w2h = sym<__half>(g_w2);

    // smem sizes: stage = ASZ + BN*80, 3 stages
    constexpr int SM_S   = 3 * (2 * 10240 + 10240);  // scores/FFN1 <128,64,64,split> 92160
    constexpr int SM_P   = 3 * (2 * 10240 + 5120);   // proj <64,64,32,split>         76800
    constexpr int SM_PV  = 3 * (10240 + 5120);       // PV  <64,64,32,nosplit>        46080

    cudaFuncSetAttribute(gemm_mma<128,64,64,0,true>, cudaFuncAttributeMaxDynamicSharedMemorySize, SM_S);
    cudaFuncSetAttribute(gemm_mma<128,64,64,5,true>, cudaFuncAttributeMaxDynamicSharedMemorySize, SM_S);
    cudaFuncSetAttribute(gemm_mma<64,64,32,1,true>,  cudaFuncAttributeMaxDynamicSharedMemorySize, SM_P);
    cudaFuncSetAttribute(gemm_mma<64,64,32,6,true>,  cudaFuncAttributeMaxDynamicSharedMemorySize, SM_P);
    cudaFuncSetAttribute(gemm_mma<64,64,32,2,true>,  cudaFuncAttributeMaxDynamicSharedMemorySize, SM_P);
    cudaFuncSetAttribute(gemm_mma<64,64,32,4,true>,  cudaFuncAttributeMaxDynamicSharedMemorySize, SM_P);
    cudaFuncSetAttribute(gemm_mma<64,64,32,3,false>, cudaFuncAttributeMaxDynamicSharedMemorySize, SM_PV);

    const dim3 blk256(256), blk128(128);

    // --- all weights -> fp16 in one kernel ---
    cvt_w<<<12288, blk256>>>((const float4*)wq, (const float4*)wk, (const float4*)wv,
                             (const float4*)wo, (const float4*)w1, (const float4*)w2,
                             (uint2*)wqh, (uint2*)wkh, (uint2*)wvh,
                             (uint2*)woh, (uint2*)w1h, (uint2*)w2h);

    // --- sublayer 1: pre-norm ---
    ln_kernel<<<S_, blk256>>>(inputs, ln1_a, ln1_b, xhi, xlo);

    // --- Q (split out), K (hi), V (hi, per-head transposed) ---
    gemm_mma<64,64,32,1,true><<<dim3(D_/64, S_/128), blk128, SM_P>>>(
        xhi, xlo, D_, 0, wqh, D_, 0, D_,
        nullptr, 0, D_, qhi, qlo, bq, nullptr, nullptr, 0.f);
    gemm_mma<64,64,32,6,true><<<dim3(D_/64, S_/128), blk128, SM_P>>>(
        xhi, xlo, D_, 0, wkh, D_, 0, D_,
        nullptr, 0, D_, khi, nullptr, bk, nullptr, nullptr, 0.f);
    gemm_mma<64,64,32,2,true><<<dim3(D_/64, S_/128), blk128, SM_P>>>(
        xhi, xlo, D_, 0, wvh, D_, 0, D_,
        nullptr, 0, D_, vthi, nullptr, bv, nullptr, nullptr, 0.f);

    // --- scores per head: S x S, K=64, masked * 1/8 ---
    gemm_mma<128,64,64,0,true><<<dim3(S_/128, S_/128, H_), blk128, SM_S>>>(
        qhi, qlo, D_, 64, khi, D_, 64, HD_,
        s, (long)S_ * S_, S_, nullptr, nullptr, nullptr, nullptr, mask, 0.125f);

    // --- entmax-1.5 (Newton) -> fp16 probs ---
    entmax_kernel<<<H_ * S_, blk256>>>(s, phi);

    // --- attended per head: S x 64, K=S (probs hi only) ---
    gemm_mma<64,64,32,3,false><<<dim3(1, S_/128, H_), blk128, SM_PV>>>(
        phi, nullptr, S_, (long)S_ * S_, vthi, S_, (long)64 * S_, S_,
        nullptr, 0, D_, athi, atlo, nullptr, nullptr, nullptr, 0.f);

    // --- output projection + residual -> y (fp32) ---
    gemm_mma<64,64,32,4,true><<<dim3(D_/64, S_/128), blk128, SM_P>>>(
        athi, atlo, D_, 0, woh, D_, 0, D_,
        y, 0, D_, nullptr, nullptr, bo, inputs, nullptr, 0.f);

    // --- sublayer 2: pre-norm ---
    ln_kernel<<<S_, blk256>>>(y, ln2_a, ln2_b, xhi, xlo);

    // --- FFN1: relu(x @ w1^T + b1) -> split ---
    gemm_mma<128,64,64,5,true><<<dim3(DFF_/128, S_/128), blk128, SM_S>>>(
        xhi, xlo, D_, 0, w1h, D_, 0, D_,
        nullptr, 0, DFF_, h1hi, h1lo, b1, nullptr, nullptr, 0.f);

    // --- FFN2 + residual -> out ---
    gemm_mma<64,64,32,4,true><<<dim3(D_/64, S_/128), blk128, SM_P>>>(
        h1hi, h1lo, DFF_, 0, w2h, DFF_, 0, DFF_,
        out, 0, D_, nullptr, nullptr, b2, y, nullptr, 0.f);
}

// round 6
// speedup vs baseline: 4.9700x; 1.4895x over previous
#include <cuda_runtime.h>
#include <cuda_fp16.h>
#include <cstdint>

#define S_   2048
#define D_   1024
#define H_   16
#define HD_  64
#define DFF_ 4096

// ---------------------------------------------------------------------------
// Device scratch (no runtime allocation allowed)
// ---------------------------------------------------------------------------
__device__ __align__(16) float  g_s  [(long)H_ * S_ * S_];   // fp32 scores
__device__ __align__(16) __half g_phi[(long)H_ * S_ * S_];   // probs (hi only)
__device__ __align__(16) __half g_xhi[S_ * D_],  g_xlo[S_ * D_];
__device__ __align__(16) __half g_qhi[S_ * D_],  g_qlo[S_ * D_];
__device__ __align__(16) __half g_khi[S_ * D_];              // hi only
__device__ __align__(16) __half g_vthi[S_ * D_];             // [h][64][S], hi only
__device__ __align__(16) __half g_ahi[S_ * D_],  g_alo[S_ * D_];
__device__ __align__(16) float  g_y  [S_ * D_];
__device__ __align__(16) __half g_h1hi[S_ * DFF_], g_h1lo[S_ * DFF_];
__device__ __align__(16) __half g_wqkv[3 * D_ * D_];         // packed q,k,v weights
__device__ __align__(16) __half g_wo[D_ * D_];
__device__ __align__(16) __half g_w1[DFF_ * D_], g_w2[D_ * DFF_];

// ---------------------------------------------------------------------------
// PTX helpers (baseline PTX only)
// ---------------------------------------------------------------------------
__device__ __forceinline__ uint32_t smem_u32(const void* p) {
    uint32_t a;
    asm("{ .reg .u64 t; cvta.to.shared.u64 t, %1; cvt.u32.u64 %0, t; }"
        : "=r"(a) : "l"(p));
    return a;
}

#define CP16(dst, src) \
    asm volatile("cp.async.cg.shared.global [%0], [%1], 16;" \
                 :: "r"(dst), "l"(src))

#define LDSM4(r, addr) \
    asm volatile("ldmatrix.sync.aligned.m8n8.x4.shared.b16 {%0,%1,%2,%3}, [%4];" \
                 : "=r"((r)[0]), "=r"((r)[1]), "=r"((r)[2]), "=r"((r)[3]) \
                 : "r"(addr))

#define MMA16816(d, a, b) \
    asm volatile("mma.sync.aligned.m16n8k16.row.col.f32.f16.f16.f32 " \
                 "{%0,%1,%2,%3}, {%4,%5,%6,%7}, {%8,%9}, {%0,%1,%2,%3};" \
                 : "+f"((d)[0]), "+f"((d)[1]), "+f"((d)[2]), "+f"((d)[3]) \
                 : "r"((a)[0]), "r"((a)[1]), "r"((a)[2]), "r"((a)[3]), \
                   "r"((b)[0]), "r"((b)[1]))

__device__ __forceinline__ uint32_t pack2(__half a, __half b) {
    __half2 h; h.x = a; h.y = b;
    return *(uint32_t*)&h;
}

__device__ __forceinline__ void split2(float v0, float v1,
                                       __half* hi, __half* lo, long idx) {
    const __half h0 = __float2half_rn(v0), h1 = __float2half_rn(v1);
    const __half l0 = __float2half_rn(v0 - __half2float(h0));
    const __half l1 = __float2half_rn(v1 - __half2float(h1));
    *(uint32_t*)(hi + idx) = pack2(h0, h1);
    *(uint32_t*)(lo + idx) = pack2(l0, l1);
}

// ---------------------------------------------------------------------------
// All 6 weight matrices -> fp16 (hi only), one fused kernel.
// q,k,v land contiguously in g_wqkv.
// ---------------------------------------------------------------------------
__global__ __launch_bounds__(256)
void cvt_w(const float4* __restrict__ wq, const float4* __restrict__ wk,
           const float4* __restrict__ wv, const float4* __restrict__ wo,
           const float4* __restrict__ w1, const float4* __restrict__ w2,
           uint2* __restrict__ oqkv, uint2* __restrict__ oo,
           uint2* __restrict__ o1, uint2* __restrict__ o2)
{
    const int i = blockIdx.x * 256 + threadIdx.x;
    const float4* s; uint2* d; int off;
    if      (i <  262144) { s = wq; d = oqkv;          off = i; }
    else if (i <  524288) { s = wk; d = oqkv + 262144; off = i -  262144; }
    else if (i <  786432) { s = wv; d = oqkv + 524288; off = i -  524288; }
    else if (i < 1048576) { s = wo; d = oo;            off = i -  786432; }
    else if (i < 2097152) { s = w1; d = o1;            off = i - 1048576; }
    else                  { s = w2; d = o2;            off = i - 2097152; }
    const float4 v = s[off];
    const __half2 a = __floats2half2_rn(v.x, v.y);
    const __half2 b = __floats2half2_rn(v.z, v.w);
    d[off] = make_uint2(*(uint32_t*)&a, *(uint32_t*)&b);
}

// ---------------------------------------------------------------------------
// LayerNorm (ddof=1 std + 1e-6) -> split-fp16 output
// ---------------------------------------------------------------------------
__global__ __launch_bounds__(256)
void ln_kernel(const float* __restrict__ X, const float* __restrict__ ga,
               const float* __restrict__ gb,
               __half* __restrict__ OH, __half* __restrict__ OL)
{
    __shared__ float sm_s[8], sm_q[8];
    const long row = blockIdx.x;
    const int tid = threadIdx.x;
    const float4 v = ((const float4*)(X + row * D_))[tid];

    float s  = v.x + v.y + v.z + v.w;
    float sq = v.x*v.x + v.y*v.y + v.z*v.z + v.w*v.w;
    #pragma unroll
    for (int o = 16; o > 0; o >>= 1) {
        s  += __shfl_xor_sync(0xffffffffu, s,  o);
        sq += __shfl_xor_sync(0xffffffffu, sq, o);
    }
    if ((tid & 31) == 0) { sm_s[tid >> 5] = s; sm_q[tid >> 5] = sq; }
    __syncthreads();
    if (tid == 0) {
        float rs = 0.f, rq = 0.f;
        #pragma unroll
        for (int w = 0; w < 8; w++) { rs += sm_s[w]; rq += sm_q[w]; }
        sm_s[0] = rs; sm_q[0] = rq;
    }
    __syncthreads();
    const float mu  = sm_s[0] * (1.0f / D_);
    const float var = fmaxf((sm_q[0] - mu * mu * (float)D_) * (1.0f / (D_ - 1)), 0.0f);
    const float inv = 1.0f / (sqrtf(var) + 1e-6f);

    const float4 a4 = ((const float4*)ga)[tid];
    const float4 b4 = ((const float4*)gb)[tid];
    const float o0 = (v.x - mu) * inv * a4.x + b4.x;
    const float o1 = (v.y - mu) * inv * a4.y + b4.y;
    const float o2 = (v.z - mu) * inv * a4.z + b4.z;
    const float o3 = (v.w - mu) * inv * a4.w + b4.w;
    const long base = row * D_ + (long)tid * 4;
    split2(o0, o1, OH, OL, base);
    split2(o2, o3, OH, OL, base + 2);
}

// ---------------------------------------------------------------------------
// entmax-1.5, one WARP per row of 2048 fp32 scores.  Row lives in 64
// registers/thread; max + 12 Newton iterations are pure shfl reductions
// (no __syncthreads, no smem).  f convex decreasing, Newton from tau=-1
// converges monotonically.  probs written fp16.
// ---------------------------------------------------------------------------
__global__ __launch_bounds__(256)
void entmax_kernel(const float* __restrict__ SC, __half* __restrict__ PH)
{
    const int wid = threadIdx.x >> 5, lane = threadIdx.x & 31;
    const long row = (long)blockIdx.x * 8 + wid;
    const float4* p4 = (const float4*)(SC + row * (long)S_);

    float x[64];
    #pragma unroll
    for (int i = 0; i < 16; i++) {
        const float4 v = p4[i * 32 + lane];
        x[4*i+0] = v.x; x[4*i+1] = v.y; x[4*i+2] = v.z; x[4*i+3] = v.w;
    }
    float mx = -3.4e38f;
    #pragma unroll
    for (int i = 0; i < 64; i++) { x[i] *= 0.5f; mx = fmaxf(mx, x[i]); }
    #pragma unroll
    for (int o = 16; o > 0; o >>= 1)
        mx = fmaxf(mx, __shfl_xor_sync(0xffffffffu, mx, o));
    #pragma unroll
    for (int i = 0; i < 64; i++) x[i] -= mx;

    float tau = -1.0f;
    #pragma unroll 1
    for (int it = 0; it < 12; it++) {
        float f = 0.f, g = 0.f;
        #pragma unroll
        for (int i = 0; i < 64; i++) {
            const float t = fmaxf(x[i] - tau, 0.f);
            f = fmaf(t, t, f);
            g += t;
        }
        #pragma unroll
        for (int o = 16; o > 0; o >>= 1) {
            f += __shfl_xor_sync(0xffffffffu, f, o);
            g += __shfl_xor_sync(0xffffffffu, g, o);
        }
        tau += (f - 1.0f) / (2.0f * g);
    }

    uint2* dst = (uint2*)(PH + row * (long)S_);
    #pragma unroll
    for (int i = 0; i < 16; i++) {
        __half h[4];
        #pragma unroll
        for (int c = 0; c < 4; c++) {
            const float t = fmaxf(x[4*i+c] - tau, 0.f);
            h[c] = __float2half_rn(t * t);
        }
        dst[i * 32 + lane] = *(const uint2*)h;
    }
}

// ---------------------------------------------------------------------------
// Warp-MMA fp16 GEMM.  C[m,n] = sum_k A[m,k]*B[n,k]  (K-major both)
// ASPLIT: acc += Ah*Bh + Al*Bh  else acc += Ah*Bh.
// Tile BM x BN x 64, warp WM x WN, 2-stage cp.async pipeline.
// MODE: 0 scores (mask+scale -> fp32), 3 plain -> split att (col += z*64),
//       4 bias+resid -> fp32, 5 bias+relu -> split,
//       7 fused QKV: z=0 -> split q, z=1 -> hi k, z=2 -> hi transposed v
// ---------------------------------------------------------------------------
template<int BM, int BN, int WM, int WN, int MODE, bool ASPLIT, int OCC>
__global__ __launch_bounds__((BM/WM)*(BN/WN)*32, OCC)
void gemm_mma(const __half* __restrict__ Ahi, const __half* __restrict__ Alo,
              int lda, long zsA,
              const __half* __restrict__ Bhi, int ldb, long zsB,
              int K,
              float* __restrict__ Cf, long zsC, int ldc,
              __half* __restrict__ Chi, __half* __restrict__ Clo,
              __half* __restrict__ Chi2, __half* __restrict__ Chi3,
              const float* __restrict__ bias, const float* __restrict__ bias2,
              const float* __restrict__ bias3,
              const float* __restrict__ resid,
              const int* __restrict__ mask, float alpha)
{
    constexpr int BK = 64;
    constexpr int WARPS_M = BM / WM, WARPS_N = BN / WN;
    constexpr int THREADS = WARPS_M * WARPS_N * 32;
    constexpr int MI = WM / 16, NJ = WN / 8;
    constexpr int LDSB   = 144;              // 128B row + 16B pad
    constexpr int ABYTES = BM * LDSB;
    constexpr int BBYTES = BN * LDSB;
    constexpr int ASZ    = ASPLIT ? 2 * ABYTES : ABYTES;
    constexpr int STAGE  = ASZ + BBYTES;

    extern __shared__ char smem[];
    const uint32_t sb = smem_u32(smem);

    const int tid  = threadIdx.x;
    const int wid  = tid >> 5;
    const int lane = tid & 31;
    const int z    = blockIdx.z;
    const int m0   = blockIdx.y * BM;
    const int n0   = blockIdx.x * BN;
    const int wtm  = (wid / WARPS_N) * WM;
    const int wtn  = (wid % WARPS_N) * WN;

    const __half* ah = Ahi + (long)z * zsA + (long)m0 * lda;
    const __half* al = ASPLIT ? (Alo + (long)z * zsA + (long)m0 * lda) : nullptr;
    const __half* bh = Bhi + (long)z * zsB + (long)n0 * ldb;

    float acc[MI][NJ][4];
    #pragma unroll
    for (int i = 0; i < MI; i++)
        #pragma unroll
        for (int j = 0; j < NJ; j++)
            #pragma unroll
            for (int r = 0; r < 4; r++) acc[i][j][r] = 0.f;

    const int nc = K / BK;

    auto load_stage = [&](int buf, int c) {
        const uint32_t base = sb + buf * STAGE;
        const int k0 = c * BK;
        #pragma unroll
        for (int it = 0; it < (BM * 8) / THREADS; it++) {
            const int ci = tid + it * THREADS;
            const int r = ci >> 3, q = ci & 7;
            const uint32_t d = base + r * LDSB + q * 16;
            CP16(d, ah + (long)r * lda + k0 + q * 8);
            if (ASPLIT)
                CP16(d + ABYTES, al + (long)r * lda + k0 + q * 8);
        }
        #pragma unroll
        for (int it = 0; it < (BN * 8) / THREADS; it++) {
            const int ci = tid + it * THREADS;
            const int r = ci >> 3, q = ci & 7;
            CP16(base + ASZ + r * LDSB + q * 16,
                 bh + (long)r * ldb + k0 + q * 8);
        }
        asm volatile("cp.async.commit_group;");
    };

    load_stage(0, 0);

    for (int c = 0; c < nc; c++) {
        if (c + 1 < nc) {
            load_stage((c + 1) & 1, c + 1);
            asm volatile("cp.async.wait_group 1;");
        } else {
            asm volatile("cp.async.wait_group 0;");
        }
        __syncthreads();

        const uint32_t base = sb + (c & 1) * STAGE;
        #pragma unroll
        for (int ks = 0; ks < 4; ks++) {
            uint32_t afh[MI][4], afl[MI][4];
            #pragma unroll
            for (int i = 0; i < MI; i++) {
                const int row = wtm + i * 16 + (lane & 15);
                const int kc  = ks * 16 + ((lane >> 4) << 3);
                const uint32_t ad = base + row * LDSB + kc * 2;
                LDSM4(afh[i], ad);
                if (ASPLIT) LDSM4(afl[i], ad + ABYTES);
            }
            uint32_t bfh[NJ][2];
            #pragma unroll
            for (int jp = 0; jp < NJ / 2; jp++) {
                const int nrow = wtn + jp * 16 + (lane & 7) + ((lane & 16) ? 8 : 0);
                const int kc   = ks * 16 + ((lane & 8) ? 8 : 0);
                uint32_t t[4];
                LDSM4(t, base + ASZ + nrow * LDSB + kc * 2);
                bfh[2*jp][0]   = t[0]; bfh[2*jp][1]   = t[1];
                bfh[2*jp+1][0] = t[2]; bfh[2*jp+1][1] = t[3];
            }
            #pragma unroll
            for (int i = 0; i < MI; i++)
                #pragma unroll
                for (int j = 0; j < NJ; j++) {
                    MMA16816(acc[i][j], afh[i], bfh[j]);
                    if (ASPLIT) MMA16816(acc[i][j], afl[i], bfh[j]);
                }
        }
        __syncthreads();
    }

    // ---- epilogue (paired stores) ----
    #pragma unroll
    for (int i = 0; i < MI; i++)
        #pragma unroll
        for (int j = 0; j < NJ; j++)
            #pragma unroll
            for (int h = 0; h < 2; h++) {
                const int row = m0 + wtm + i * 16 + (lane >> 2) + h * 8;
                const int col = n0 + wtn + j * 8 + (lane & 3) * 2;
                float v0 = acc[i][j][2*h], v1 = acc[i][j][2*h+1];
                if (MODE == 0) {
                    v0 = mask[col]     ? v0 * alpha : -1e9f;
                    v1 = mask[col + 1] ? v1 * alpha : -1e9f;
                    *(float2*)(Cf + (long)z * zsC + (long)row * ldc + col)
                        = make_float2(v0, v1);
                } else if (MODE == 3) {
                    split2(v0, v1, Chi, Clo, (long)row * ldc + z * 64 + col);
                } else if (MODE == 4) {
                    const long idx = (long)row * ldc + col;
                    const float2 b2 = *(const float2*)(bias + col);
                    const float2 r2 = *(const float2*)(resid + idx);
                    *(float2*)(Cf + idx) = make_float2(v0 + b2.x + r2.x,
                                                       v1 + b2.y + r2.y);
                } else if (MODE == 5) {
                    const float2 b2 = *(const float2*)(bias + col);
                    v0 = fmaxf(v0 + b2.x, 0.f); v1 = fmaxf(v1 + b2.y, 0.f);
                    split2(v0, v1, Chi, Clo, (long)row * ldc + col);
                } else {  // MODE 7: fused QKV
                    const float* bp = (z == 0) ? bias : (z == 1 ? bias2 : bias3);
                    const float2 b2 = *(const float2*)(bp + col);
                    v0 += b2.x; v1 += b2.y;
                    if (z == 0) {
                        split2(v0, v1, Chi, Clo, (long)row * ldc + col);
                    } else if (z == 1) {
                        *(uint32_t*)(Chi2 + (long)row * ldc + col)
                            = pack2(__float2half_rn(v0), __float2half_rn(v1));
                    } else {
                        Chi3[(long)col * S_ + row]       = __float2half_rn(v0);
                        Chi3[(long)(col + 1) * S_ + row] = __float2half_rn(v1);
                    }
                }
            }
}

// ---------------------------------------------------------------------------
// Launch
// ---------------------------------------------------------------------------
template<typename T>
static T* sym(const void* s) {
    void* p = nullptr;
    cudaGetSymbolAddress(&p, s);
    return (T*)p;
}

extern "C" void kernel_launch(void* const* d_in, const int* in_sizes, int n_in,
                              void* d_out, int out_size)
{
    const float* inputs = (const float*)d_in[0];
    const int*   mask   = (const int*)  d_in[1];
    const float* wq = (const float*)d_in[2];  const float* bq = (const float*)d_in[3];
    const float* wk = (const float*)d_in[4];  const float* bk = (const float*)d_in[5];
    const float* wv = (const float*)d_in[6];  const float* bv = (const float*)d_in[7];
    const float* wo = (const float*)d_in[8];  const float* bo = (const float*)d_in[9];
    const float* ln1_a = (const float*)d_in[10]; const float* ln1_b = (const float*)d_in[11];
    const float* w1 = (const float*)d_in[12]; const float* b1 = (const float*)d_in[13];
    const float* w2 = (const float*)d_in[14]; const float* b2 = (const float*)d_in[15];
    const float* ln2_a = (const float*)d_in[16]; const float* ln2_b = (const float*)d_in[17];
    float* out = (float*)d_out;

    float* s    = sym<float>(g_s);
    __half *phi = sym<__half>(g_phi);
    __half *xhi = sym<__half>(g_xhi), *xlo = sym<__half>(g_xlo);
    __half *qhi = sym<__half>(g_qhi), *qlo = sym<__half>(g_qlo);
    __half *khi = sym<__half>(g_khi);
    __half *vthi = sym<__half>(g_vthi);
    __half *athi = sym<__half>(g_ahi), *atlo = sym<__half>(g_alo);
    float* y = sym<float>(g_y);
    __half *h1hi = sym<__half>(g_h1hi), *h1lo = sym<__half>(g_h1lo);
    __half *wqkv = sym<__half>(g_wqkv);
    __half *woh = sym<__half>(g_wo);
    __half *w1h = sym<__half>(g_w1), *w2h = sym<__half>(g_w2);

    // stage = ASZ + BN*144
    constexpr int SM_P  = 2 * (2 * 64 * 144 + 64 * 144);    // 55296  (64x64 split)
    constexpr int SM_PV = 2 * (64 * 144 + 64 * 144);        // 36864  (64x64 nosplit)
    constexpr int SM_SC = 1 * (2 * 128 * 144 + 128 * 144);  // 55296  (scores, nc=1)
    constexpr int SM_F1 = 2 * (2 * 128 * 144 + 128 * 144);  // 110592 (FFN1)

    cudaFuncSetAttribute((const void*)gemm_mma<64,64,32,32,7,true,4>,
                         cudaFuncAttributeMaxDynamicSharedMemorySize, SM_P);
    cudaFuncSetAttribute((const void*)gemm_mma<64,64,32,32,4,true,4>,
                         cudaFuncAttributeMaxDynamicSharedMemorySize, SM_P);
    cudaFuncSetAttribute((const void*)gemm_mma<64,64,32,32,3,false,4>,
                         cudaFuncAttributeMaxDynamicSharedMemorySize, SM_PV);
    cudaFuncSetAttribute((const void*)gemm_mma<128,128,64,64,0,true,2>,
                         cudaFuncAttributeMaxDynamicSharedMemorySize, SM_SC);
    cudaFuncSetAttribute((const void*)gemm_mma<128,128,64,64,5,true,2>,
                         cudaFuncAttributeMaxDynamicSharedMemorySize, SM_F1);

    const dim3 blk256(256), blk128(128);

    // --- all weights -> fp16 (q,k,v packed) ---
    cvt_w<<<12288, blk256>>>((const float4*)wq, (const float4*)wk, (const float4*)wv,
                             (const float4*)wo, (const float4*)w1, (const float4*)w2,
                             (uint2*)wqkv, (uint2*)woh, (uint2*)w1h, (uint2*)w2h);

    // --- sublayer 1: pre-norm ---
    ln_kernel<<<S_, blk256>>>(inputs, ln1_a, ln1_b, xhi, xlo);

    // --- fused QKV: grid (16, 32, 3) = 1536 CTAs ---
    gemm_mma<64,64,32,32,7,true,4><<<dim3(D_/64, S_/64, 3), blk128, SM_P>>>(
        xhi, xlo, D_, 0, wqkv, D_, (long)D_ * D_, D_,
        nullptr, 0, D_, qhi, qlo, khi, vthi,
        bq, bk, bv, nullptr, nullptr, 0.f);

    // --- scores per head: S x S, K=64, masked * 1/8 ---
    gemm_mma<128,128,64,64,0,true,2><<<dim3(S_/128, S_/128, H_), blk128, SM_SC>>>(
        qhi, qlo, D_, 64, khi, D_, 64, HD_,
        s, (long)S_ * S_, S_, nullptr, nullptr, nullptr, nullptr,
        nullptr, nullptr, nullptr, nullptr, mask, 0.125f);

    // --- entmax-1.5 (warp-per-row Newton) -> fp16 probs ---
    entmax_kernel<<<H_ * S_ / 8, blk256>>>(s, phi);

    // --- attended per head: S x 64, K=S ---
    gemm_mma<64,64,32,32,3,false,4><<<dim3(1, S_/64, H_), blk128, SM_PV>>>(
        phi, nullptr, S_, (long)S_ * S_, vthi, S_, (long)64 * S_, S_,
        nullptr, 0, D_, athi, atlo, nullptr, nullptr,
        nullptr, nullptr, nullptr, nullptr, nullptr, 0.f);

    // --- output projection + residual -> y (fp32) ---
    gemm_mma<64,64,32,32,4,true,4><<<dim3(D_/64, S_/64), blk128, SM_P>>>(
        athi, atlo, D_, 0, woh, D_, 0, D_,
        y, 0, D_, nullptr, nullptr, nullptr, nullptr,
        bo, nullptr, nullptr, inputs, nullptr, 0.f);

    // --- sublayer 2: pre-norm ---
    ln_kernel<<<S_, blk256>>>(y, ln2_a, ln2_b, xhi, xlo);

    // --- FFN1: relu(x @ w1^T + b1) -> split ---
    gemm_mma<128,128,64,64,5,true,2><<<dim3(DFF_/128, S_/128), blk128, SM_F1>>>(
        xhi, xlo, D_, 0, w1h, D_, 0, D_,
        nullptr, 0, DFF_, h1hi, h1lo, nullptr, nullptr,
        b1, nullptr, nullptr, nullptr, nullptr, 0.f);

    // --- FFN2 + residual -> out ---
    gemm_mma<64,64,32,32,4,true,4><<<dim3(D_/64, S_/64), blk128, SM_P>>>(
        h1hi, h1lo, DFF_, 0, w2h, DFF_, 0, DFF_,
        out, 0, D_, nullptr, nullptr, nullptr, nullptr,
        b2, nullptr, nullptr, y, nullptr, 0.f);
}